// round 6
// baseline (speedup 1.0000x reference)
#include <cuda_runtime.h>
#include <math.h>

// Problem-fixed sizes
#define PN 200000
#define PE 800000
#define LN 100000
#define LE 400000
#define NB 512

// ---------------- scratch (static device globals; no allocation) ----------------
__device__ float g_pA[(size_t)PN * 256];
__device__ float g_pB[(size_t)PN * 256];
__device__ float g_pC[(size_t)PN * 256];
__device__ float g_lA[(size_t)LN * 256];
__device__ float g_lB[(size_t)LN * 256];
__device__ float g_lC[(size_t)LN * 256];
__device__ float g_deg[PN];
__device__ float g_pdinv[PN];
__device__ float g_ldinv[LN];
__device__ float g_pool[NB * 256];
__device__ int   g_cnt[NB];
__device__ float g_cat[NB * 512];
__device__ float g_fc1[NB * 1024];
__device__ float g_fc2[NB * 512];

// ---------------- small utility kernels ----------------
__global__ void fill_f(float* p, float v, int n) {
    int i = blockIdx.x * blockDim.x + threadIdx.x;
    if (i < n) p[i] = v;
}
__global__ void fill_i(int* p, int v, int n) {
    int i = blockIdx.x * blockDim.x + threadIdx.x;
    if (i < n) p[i] = v;
}
__global__ void deg_count(float* deg, const int* __restrict__ dst, int E) {
    int i = blockIdx.x * blockDim.x + threadIdx.x;
    if (i < E) atomicAdd(&deg[dst[i]], 1.0f);
}
__global__ void rsqrt_k(float* dinv, const float* __restrict__ deg, int n) {
    int i = blockIdx.x * blockDim.x + threadIdx.x;
    if (i < n) dinv[i] = rsqrtf(deg[i]);
}
__global__ void cnt_k(int* cnt, const int* __restrict__ batch, int n) {
    int i = blockIdx.x * blockDim.x + threadIdx.x;
    if (i < n) atomicAdd(&cnt[batch[i]], 1);
}

// ---------------- tiled fp32 GEMM: C = epilogue(A[MxK] @ B[KxN]) ----------------
// epilogue: v = acc; if(bias) v += bias[col]; if(rowscale) v *= rowscale[row];
//           if(relu) v = max(v,0); C0 = v; if(C1) C1 = v;
#define BM 64
#define BN 64
#define BKK 8
#define TM 4
#define TN 4

__global__ __launch_bounds__(256) void sgemm_kernel(
    const float* __restrict__ A, const float* __restrict__ Bm,
    int M, int N, int K,
    float* __restrict__ C0, float* __restrict__ C1,
    const float* __restrict__ rowscale,
    const float* __restrict__ bias, int do_relu)
{
    __shared__ float As[BM][BKK];
    __shared__ float Bs[BKK][BN];
    int tid = threadIdx.x;
    int tx = tid % 16, ty = tid / 16;
    int row0 = blockIdx.y * BM, col0 = blockIdx.x * BN;

    float acc[TM][TN] = {};

    for (int kk = 0; kk < K; kk += BKK) {
        // A tile: 64x8 = 512 elems / 256 threads
        #pragma unroll
        for (int i = tid; i < BM * BKK; i += 256) {
            int r = i / BKK, c = i % BKK;
            int gr = row0 + r, gc = kk + c;
            As[r][c] = (gr < M && gc < K) ? A[(size_t)gr * K + gc] : 0.f;
        }
        // B tile: 8x64 = 512 elems / 256 threads
        #pragma unroll
        for (int i = tid; i < BKK * BN; i += 256) {
            int r = i / BN, c = i % BN;
            int gr = kk + r, gc = col0 + c;
            Bs[r][c] = (gr < K && gc < N) ? Bm[(size_t)gr * N + gc] : 0.f;
        }
        __syncthreads();
        #pragma unroll
        for (int k = 0; k < BKK; k++) {
            float a[TM], b[TN];
            #pragma unroll
            for (int i = 0; i < TM; i++) a[i] = As[ty * TM + i][k];
            #pragma unroll
            for (int j = 0; j < TN; j++) b[j] = Bs[k][tx * TN + j];
            #pragma unroll
            for (int i = 0; i < TM; i++)
                #pragma unroll
                for (int j = 0; j < TN; j++)
                    acc[i][j] = fmaf(a[i], b[j], acc[i][j]);
        }
        __syncthreads();
    }

    #pragma unroll
    for (int i = 0; i < TM; i++) {
        int gr = row0 + ty * TM + i;
        if (gr >= M) continue;
        float rs = rowscale ? rowscale[gr] : 1.f;
        #pragma unroll
        for (int j = 0; j < TN; j++) {
            int gc = col0 + tx * TN + j;
            if (gc >= N) continue;
            float v = acc[i][j];
            if (bias) v += bias[gc];
            v *= rs;
            if (do_relu) v = fmaxf(v, 0.f);
            size_t idx = (size_t)gr * N + gc;
            C0[idx] = v;
            if (C1) C1[idx] = v;
        }
    }
}

// ---------------- edge scatter: acc[dst] += h[src], one warp per edge ----------------
template <int F>
__global__ void scatter_add(const float* __restrict__ h, float* __restrict__ acc,
                            const int* __restrict__ src, const int* __restrict__ dst, int E)
{
    int gw = (blockIdx.x * blockDim.x + threadIdx.x) >> 5;
    int lane = threadIdx.x & 31;
    if (gw >= E) return;
    int s = src[gw], d = dst[gw];
    const float* hs = h + (size_t)s * F;
    float* ad = acc + (size_t)d * F;
    #pragma unroll
    for (int j = 0; j < F / 32; j++)
        atomicAdd(ad + lane + j * 32, hs[lane + j * 32]);
}

// ---------------- layer finish: out = relu(acc * dinv[row] + bias[col]) ----------------
template <int F>
__global__ void gcn_finish(const float* __restrict__ acc, const float* __restrict__ dinv,
                           const float* __restrict__ bias, float* __restrict__ out, int n_nodes)
{
    size_t i = (size_t)blockIdx.x * blockDim.x + threadIdx.x;
    size_t total = (size_t)n_nodes * F;
    if (i >= total) return;
    int row = (int)(i / F);
    int col = (int)(i & (F - 1));
    float v = fmaf(acc[i], dinv[row], bias[col]);
    out[i] = fmaxf(v, 0.f);
}

// ---------------- pooling ----------------
__global__ void pool_scatter(const float* __restrict__ x, const int* __restrict__ batch,
                             float* __restrict__ pool, int N)
{
    int gw = (blockIdx.x * blockDim.x + threadIdx.x) >> 5;
    int lane = threadIdx.x & 31;
    if (gw >= N) return;
    int b = batch[gw];
    const float* xr = x + (size_t)gw * 256;
    float* pr = pool + (size_t)b * 256;
    #pragma unroll
    for (int j = 0; j < 8; j++)
        atomicAdd(pr + lane + j * 32, xr[lane + j * 32]);
}

__global__ void pool_fin(const float* __restrict__ pool, const int* __restrict__ cnt,
                         float* __restrict__ cat, int off)
{
    int b = blockIdx.x;
    float inv = 1.0f / fmaxf((float)cnt[b], 1.0f);
    for (int c = threadIdx.x; c < 256; c += blockDim.x)
        cat[b * 512 + off + c] = pool[b * 256 + c] * inv;
}

// ---------------- final linear head: out[b] = dot(X[b,:512], W) + bias ----------------
__global__ void out_kernel(const float* __restrict__ X, const float* __restrict__ W,
                           const float* __restrict__ bias, float* __restrict__ out)
{
    int b = blockIdx.x;
    __shared__ float red[256];
    float s = 0.f;
    for (int k = threadIdx.x; k < 512; k += 256)
        s += X[b * 512 + k] * W[k];
    red[threadIdx.x] = s;
    __syncthreads();
    for (int off = 128; off > 0; off >>= 1) {
        if (threadIdx.x < off) red[threadIdx.x] += red[threadIdx.x + off];
        __syncthreads();
    }
    if (threadIdx.x == 0) out[b] = red[0] + bias[0];
}

// ---------------- host side ----------------
static inline void sgemm(const float* A, const float* B, int M, int N, int K,
                         float* C0, float* C1, const float* rs, const float* bias, int relu)
{
    dim3 grid((N + BN - 1) / BN, (M + BM - 1) / BM);
    sgemm_kernel<<<grid, 256>>>(A, B, M, N, K, C0, C1, rs, bias, relu);
}

static void run_branch(const float* x, int Fin, int N, int E,
                       const int* src, const int* dst, const int* batch,
                       const float* W1, const float* b1,
                       const float* W2, const float* b2,
                       const float* W3, const float* b3,
                       float* A, float* Bf, float* C,
                       float* deg, float* dinv,
                       float* pool, int* cnt, float* cat, int catoff)
{
    // degrees + norm
    fill_f<<<(N + 255) / 256, 256>>>(deg, 1.0f, N);
    deg_count<<<(E + 255) / 256, 256>>>(deg, dst, E);
    rsqrt_k<<<(N + 255) / 256, 256>>>(dinv, deg, N);

    // layer 1: Fin -> 64
    sgemm(x, W1, N, 64, Fin, A, Bf, dinv, nullptr, 0);
    {
        int blocks = (E * 32 + 255) / 256;
        scatter_add<64><<<blocks, 256>>>(A, Bf, src, dst, E);
        int tb = (int)(((size_t)N * 64 + 255) / 256);
        gcn_finish<64><<<tb, 256>>>(Bf, dinv, b1, C, N);
    }
    // layer 2: 64 -> 128
    sgemm(C, W2, N, 128, 64, A, Bf, dinv, nullptr, 0);
    {
        int blocks = (E * 32 + 255) / 256;
        scatter_add<128><<<blocks, 256>>>(A, Bf, src, dst, E);
        int tb = (int)(((size_t)N * 128 + 255) / 256);
        gcn_finish<128><<<tb, 256>>>(Bf, dinv, b2, C, N);
    }
    // layer 3: 128 -> 256
    sgemm(C, W3, N, 256, 128, A, Bf, dinv, nullptr, 0);
    {
        int blocks = (E * 32 + 255) / 256;
        scatter_add<256><<<blocks, 256>>>(A, Bf, src, dst, E);
        int tb = (int)(((size_t)N * 256 + 255) / 256);
        gcn_finish<256><<<tb, 256>>>(Bf, dinv, b3, C, N);
    }

    // mean pool -> cat[:, catoff:catoff+256]
    fill_f<<<(NB * 256 + 255) / 256, 256>>>(pool, 0.f, NB * 256);
    fill_i<<<(NB + 255) / 256, 256>>>(cnt, 0, NB);
    cnt_k<<<(N + 255) / 256, 256>>>(cnt, batch, N);
    pool_scatter<<<(N * 32 + 255) / 256, 256>>>(C, batch, pool, N);
    pool_fin<<<NB, 256>>>(pool, cnt, cat, catoff);
}

extern "C" void kernel_launch(void* const* d_in, const int* in_sizes, int n_in,
                              void* d_out, int out_size)
{
    const float* p_x    = (const float*)d_in[0];
    const int*   p_ei   = (const int*)d_in[1];
    const int*   p_bat  = (const int*)d_in[2];
    const float* l_x    = (const float*)d_in[3];
    const int*   l_ei   = (const int*)d_in[4];
    const int*   l_bat  = (const int*)d_in[5];
    const float* p_W1 = (const float*)d_in[6],  *p_b1 = (const float*)d_in[7];
    const float* p_W2 = (const float*)d_in[8],  *p_b2 = (const float*)d_in[9];
    const float* p_W3 = (const float*)d_in[10], *p_b3 = (const float*)d_in[11];
    const float* l_W1 = (const float*)d_in[12], *l_b1 = (const float*)d_in[13];
    const float* l_W2 = (const float*)d_in[14], *l_b2 = (const float*)d_in[15];
    const float* l_W3 = (const float*)d_in[16], *l_b3 = (const float*)d_in[17];
    const float* fc1_W = (const float*)d_in[18], *fc1_b = (const float*)d_in[19];
    const float* fc2_W = (const float*)d_in[20], *fc2_b = (const float*)d_in[21];
    const float* out_W = (const float*)d_in[22], *out_b = (const float*)d_in[23];
    float* out = (float*)d_out;

    float *pA, *pB, *pC, *lA, *lB, *lC, *deg, *pdinv, *ldinv, *pool, *cat, *fc1, *fc2;
    int* cnt;
    cudaGetSymbolAddress((void**)&pA, g_pA);
    cudaGetSymbolAddress((void**)&pB, g_pB);
    cudaGetSymbolAddress((void**)&pC, g_pC);
    cudaGetSymbolAddress((void**)&lA, g_lA);
    cudaGetSymbolAddress((void**)&lB, g_lB);
    cudaGetSymbolAddress((void**)&lC, g_lC);
    cudaGetSymbolAddress((void**)&deg, g_deg);
    cudaGetSymbolAddress((void**)&pdinv, g_pdinv);
    cudaGetSymbolAddress((void**)&ldinv, g_ldinv);
    cudaGetSymbolAddress((void**)&pool, g_pool);
    cudaGetSymbolAddress((void**)&cnt, g_cnt);
    cudaGetSymbolAddress((void**)&cat, g_cat);
    cudaGetSymbolAddress((void**)&fc1, g_fc1);
    cudaGetSymbolAddress((void**)&fc2, g_fc2);

    // p branch: src = p_ei[0:E], dst = p_ei[E:2E]
    run_branch(p_x, 41, PN, PE, p_ei, p_ei + PE, p_bat,
               p_W1, p_b1, p_W2, p_b2, p_W3, p_b3,
               pA, pB, pC, deg, pdinv, pool, cnt, cat, /*catoff=*/0);

    // l branch
    run_branch(l_x, 78, LN, LE, l_ei, l_ei + LE, l_bat,
               l_W1, l_b1, l_W2, l_b2, l_W3, l_b3,
               lA, lB, lC, deg, ldinv, pool, cnt, cat, /*catoff=*/256);

    // MLP head
    sgemm(cat, fc1_W, NB, 1024, 512, fc1, nullptr, nullptr, fc1_b, 1);
    sgemm(fc1, fc2_W, NB, 512, 1024, fc2, nullptr, nullptr, fc2_b, 1);
    out_kernel<<<NB, 256>>>(fc2, out_W, out_b, out);
}

// round 9
// speedup vs baseline: 1.2045x; 1.2045x over previous
#include <cuda_runtime.h>
#include <math.h>

// Problem-fixed sizes
#define PN 200000
#define PE 800000
#define LN 100000
#define LE 400000
#define NB 512

// ---------------- scratch (static device globals; no allocation) ----------------
__device__ float g_pA[(size_t)PN * 256];
__device__ float g_pB[(size_t)PN * 256];
__device__ float g_pC[(size_t)PN * 256];
__device__ float g_lA[(size_t)LN * 256];
__device__ float g_lB[(size_t)LN * 256];
__device__ float g_lC[(size_t)LN * 256];
__device__ float g_deg[PN];
__device__ float g_pdinv[PN];
__device__ float g_ldinv[LN];
__device__ float g_cat[NB * 512];
__device__ float g_fc1[NB * 1024];
__device__ float g_fc2[NB * 512];

// ---------------- small utility kernels ----------------
__global__ void fill_f(float* p, float v, int n) {
    int i = blockIdx.x * blockDim.x + threadIdx.x;
    if (i < n) p[i] = v;
}
__global__ void deg_count(float* deg, const int* __restrict__ dst, int E) {
    int i = blockIdx.x * blockDim.x + threadIdx.x;
    if (i < E) atomicAdd(&deg[dst[i]], 1.0f);
}
__global__ void rsqrt_k(float* dinv, const float* __restrict__ deg, int n) {
    int i = blockIdx.x * blockDim.x + threadIdx.x;
    if (i < n) dinv[i] = rsqrtf(deg[i]);
}

// ---------------- slow-path GEMM (odd K / small N: layer 1 only) ----------------
#define BM0 64
#define BN0 64
#define BK0 8
#define TM0 4
#define TN0 4

__global__ __launch_bounds__(256) void sgemm_kernel(
    const float* __restrict__ A, const float* __restrict__ Bm,
    int M, int N, int K,
    float* __restrict__ C0, float* __restrict__ C1,
    const float* __restrict__ rowscale,
    const float* __restrict__ bias, int do_relu)
{
    __shared__ float As[BM0][BK0];
    __shared__ float Bs[BK0][BN0];
    int tid = threadIdx.x;
    int tx = tid % 16, ty = tid / 16;
    int row0 = blockIdx.y * BM0, col0 = blockIdx.x * BN0;

    float acc[TM0][TN0] = {};

    for (int kk = 0; kk < K; kk += BK0) {
        #pragma unroll
        for (int i = tid; i < BM0 * BK0; i += 256) {
            int r = i / BK0, c = i % BK0;
            int gr = row0 + r, gc = kk + c;
            As[r][c] = (gr < M && gc < K) ? A[(size_t)gr * K + gc] : 0.f;
        }
        #pragma unroll
        for (int i = tid; i < BK0 * BN0; i += 256) {
            int r = i / BN0, c = i % BN0;
            int gr = kk + r, gc = col0 + c;
            Bs[r][c] = (gr < K && gc < N) ? Bm[(size_t)gr * N + gc] : 0.f;
        }
        __syncthreads();
        #pragma unroll
        for (int k = 0; k < BK0; k++) {
            float a[TM0], b[TN0];
            #pragma unroll
            for (int i = 0; i < TM0; i++) a[i] = As[ty * TM0 + i][k];
            #pragma unroll
            for (int j = 0; j < TN0; j++) b[j] = Bs[k][tx * TN0 + j];
            #pragma unroll
            for (int i = 0; i < TM0; i++)
                #pragma unroll
                for (int j = 0; j < TN0; j++)
                    acc[i][j] = fmaf(a[i], b[j], acc[i][j]);
        }
        __syncthreads();
    }

    #pragma unroll
    for (int i = 0; i < TM0; i++) {
        int gr = row0 + ty * TM0 + i;
        if (gr >= M) continue;
        float rs = rowscale ? rowscale[gr] : 1.f;
        #pragma unroll
        for (int j = 0; j < TN0; j++) {
            int gc = col0 + tx * TN0 + j;
            if (gc >= N) continue;
            float v = acc[i][j];
            if (bias) v += bias[gc];
            v *= rs;
            if (do_relu) v = fmaxf(v, 0.f);
            size_t idx = (size_t)gr * N + gc;
            C0[idx] = v;
            if (C1) C1[idx] = v;
        }
    }
}

// ---------------- fast GEMM: 128x128 tile, 8x8 microtile, float4 everywhere ----
// Requires: K % 8 == 0, K % 4 == 0, N % BN == 0. Row guard on M only.
template<int BM, int BN, int TM, int TN>
__global__ __launch_bounds__(256) void sgemm_fast(
    const float* __restrict__ A, const float* __restrict__ Bm,
    int M, int N, int K,
    float* __restrict__ C0, float* __restrict__ C1,
    const float* __restrict__ rowscale,
    const float* __restrict__ bias, int do_relu)
{
    constexpr int BK = 8;
    constexpr int TX = BN / TN;   // thread columns
    __shared__ float As[BK][BM];
    __shared__ float Bs[BK][BN];
    const int tid = threadIdx.x;
    const int row0 = blockIdx.y * BM;
    const int col0 = blockIdx.x * BN;
    const int tx = tid % TX, ty = tid / TX;

    float acc[TM][TN];
    #pragma unroll
    for (int i = 0; i < TM; i++)
        #pragma unroll
        for (int j = 0; j < TN; j++) acc[i][j] = 0.f;

    for (int kk = 0; kk < K; kk += BK) {
        // A tile: BM x BK, load float4 along K, store transposed As[k][m]
        #pragma unroll
        for (int f = tid; f < BM * BK / 4; f += 256) {
            int m = f >> 1;                // BK/4 = 2 float4 per row
            int kq = (f & 1) * 4;
            int gr = row0 + m;
            float4 v = make_float4(0.f, 0.f, 0.f, 0.f);
            if (gr < M)
                v = *reinterpret_cast<const float4*>(&A[(size_t)gr * K + kk + kq]);
            As[kq + 0][m] = v.x;
            As[kq + 1][m] = v.y;
            As[kq + 2][m] = v.z;
            As[kq + 3][m] = v.w;
        }
        // B tile: BK x BN, float4 along N
        #pragma unroll
        for (int f = tid; f < BK * BN / 4; f += 256) {
            int k = f / (BN / 4);
            int nq = (f % (BN / 4)) * 4;
            float4 v = *reinterpret_cast<const float4*>(&Bm[(size_t)(kk + k) * N + col0 + nq]);
            *reinterpret_cast<float4*>(&Bs[k][nq]) = v;
        }
        __syncthreads();

        #pragma unroll
        for (int k = 0; k < BK; k++) {
            float a[TM], b[TN];
            #pragma unroll
            for (int i = 0; i < TM; i += 4)
                *reinterpret_cast<float4*>(&a[i]) =
                    *reinterpret_cast<const float4*>(&As[k][ty * TM + i]);
            #pragma unroll
            for (int j = 0; j < TN; j += 4)
                *reinterpret_cast<float4*>(&b[j]) =
                    *reinterpret_cast<const float4*>(&Bs[k][tx * TN + j]);
            #pragma unroll
            for (int i = 0; i < TM; i++)
                #pragma unroll
                for (int j = 0; j < TN; j++)
                    acc[i][j] = fmaf(a[i], b[j], acc[i][j]);
        }
        __syncthreads();
    }

    #pragma unroll
    for (int i = 0; i < TM; i++) {
        int gr = row0 + ty * TM + i;
        if (gr >= M) continue;
        float rs = rowscale ? rowscale[gr] : 1.f;
        float v[TN];
        #pragma unroll
        for (int j = 0; j < TN; j++) {
            int gc = col0 + tx * TN + j;
            float t = acc[i][j];
            if (bias) t += bias[gc];
            t *= rs;
            if (do_relu) t = fmaxf(t, 0.f);
            v[j] = t;
        }
        size_t base = (size_t)gr * N + col0 + tx * TN;
        #pragma unroll
        for (int j = 0; j < TN; j += 4) {
            float4 q = *reinterpret_cast<float4*>(&v[j]);
            *reinterpret_cast<float4*>(&C0[base + j]) = q;
            if (C1) *reinterpret_cast<float4*>(&C1[base + j]) = q;
        }
    }
}

// ---------------- edge scatter: one float4 per thread, red.global.add.v4 -------
template <int F>
__global__ void scatter_add_v4(const float* __restrict__ h, float* __restrict__ acc,
                               const int* __restrict__ src, const int* __restrict__ dst,
                               int E)
{
    constexpr int S = F / 4;  // float4 slots per edge
    long long t = (long long)blockIdx.x * blockDim.x + threadIdx.x;
    if (t >= (long long)E * S) return;
    int e = (int)(t / S);
    int slot = (int)(t % S);
    int s = src[e], d = dst[e];
    float4 v = *reinterpret_cast<const float4*>(h + (size_t)s * F + slot * 4);
    float* p = acc + (size_t)d * F + slot * 4;
    asm volatile("red.global.add.v4.f32 [%0], {%1, %2, %3, %4};"
                 :: "l"(p), "f"(v.x), "f"(v.y), "f"(v.z), "f"(v.w)
                 : "memory");
}

// ---------------- layer finish: out = relu(acc * dinv[row] + bias[col]) --------
template <int F>
__global__ void gcn_finish_v4(const float* __restrict__ acc, const float* __restrict__ dinv,
                              const float* __restrict__ bias, float* __restrict__ out,
                              int n_nodes)
{
    size_t i = (size_t)blockIdx.x * blockDim.x + threadIdx.x;  // float4 index
    size_t total = (size_t)n_nodes * (F / 4);
    if (i >= total) return;
    int row = (int)(i / (F / 4));
    int c4 = (int)(i % (F / 4)) * 4;
    float di = dinv[row];
    float4 a = reinterpret_cast<const float4*>(acc)[i];
    float4 o;
    o.x = fmaxf(fmaf(a.x, di, bias[c4 + 0]), 0.f);
    o.y = fmaxf(fmaf(a.y, di, bias[c4 + 1]), 0.f);
    o.z = fmaxf(fmaf(a.z, di, bias[c4 + 2]), 0.f);
    o.w = fmaxf(fmaf(a.w, di, bias[c4 + 3]), 0.f);
    reinterpret_cast<float4*>(out)[i] = o;
}

// ---------------- segmented mean-pool (batch is sorted) ------------------------
// block b: binary-search its node range, sum 256 columns, write cat directly.
__global__ void pool_seg(const float* __restrict__ x, const int* __restrict__ batch,
                         int N, float* __restrict__ cat, int off)
{
    int b = blockIdx.x;
    int l = 0, r = N;
    while (l < r) { int m = (l + r) >> 1; if (batch[m] < b) l = m + 1; else r = m; }
    int start = l;
    r = N;
    while (l < r) { int m = (l + r) >> 1; if (batch[m] < b + 1) l = m + 1; else r = m; }
    int end = l;
    int c = threadIdx.x;  // 256 threads, one column each
    float s = 0.f;
    for (int i = start; i < end; i++)
        s += x[(size_t)i * 256 + c];
    float cnt = (float)(end - start);
    cat[b * 512 + off + c] = s / fmaxf(cnt, 1.f);
}

// ---------------- final linear head ----------------
__global__ void out_kernel(const float* __restrict__ X, const float* __restrict__ W,
                           const float* __restrict__ bias, float* __restrict__ out)
{
    int b = blockIdx.x;
    __shared__ float red[256];
    float s = 0.f;
    for (int k = threadIdx.x; k < 512; k += 256)
        s += X[b * 512 + k] * W[k];
    red[threadIdx.x] = s;
    __syncthreads();
    for (int off = 128; off > 0; off >>= 1) {
        if (threadIdx.x < off) red[threadIdx.x] += red[threadIdx.x + off];
        __syncthreads();
    }
    if (threadIdx.x == 0) out[b] = red[0] + bias[0];
}

// ---------------- host side ----------------
static inline void sgemm_slow(const float* A, const float* B, int M, int N, int K,
                              float* C0, float* C1, const float* rs, const float* bias,
                              int relu)
{
    dim3 grid((N + BN0 - 1) / BN0, (M + BM0 - 1) / BM0);
    sgemm_kernel<<<grid, 256>>>(A, B, M, N, K, C0, C1, rs, bias, relu);
}

static inline void sgemm_f(const float* A, const float* B, int M, int N, int K,
                           float* C0, float* C1, const float* rs, const float* bias,
                           int relu)
{
    // fast path: K%8==0, N%128==0
    dim3 grid(N / 128, (M + 127) / 128);
    sgemm_fast<128, 128, 8, 8><<<grid, 256>>>(A, B, M, N, K, C0, C1, rs, bias, relu);
}

template <int F>
static inline void scatter(const float* h, float* acc, const int* src, const int* dst, int E)
{
    long long total = (long long)E * (F / 4);
    int blocks = (int)((total + 255) / 256);
    scatter_add_v4<F><<<blocks, 256>>>(h, acc, src, dst, E);
}

template <int F>
static inline void finish(const float* acc, const float* dinv, const float* bias,
                          float* out, int N)
{
    size_t total = (size_t)N * (F / 4);
    int blocks = (int)((total + 255) / 256);
    gcn_finish_v4<F><<<blocks, 256>>>(acc, dinv, bias, out, N);
}

static void run_branch(const float* x, int Fin, int N, int E,
                       const int* src, const int* dst, const int* batch,
                       const float* W1, const float* b1,
                       const float* W2, const float* b2,
                       const float* W3, const float* b3,
                       float* A, float* Bf, float* C,
                       float* deg, float* dinv,
                       float* cat, int catoff)
{
    // degrees + symmetric norm
    fill_f<<<(N + 255) / 256, 256>>>(deg, 1.0f, N);
    deg_count<<<(E + 255) / 256, 256>>>(deg, dst, E);
    rsqrt_k<<<(N + 255) / 256, 256>>>(dinv, deg, N);

    // layer 1: Fin -> 64   (odd K, N=64 -> slow path)
    sgemm_slow(x, W1, N, 64, Fin, A, Bf, dinv, nullptr, 0);
    scatter<64>(A, Bf, src, dst, E);
    finish<64>(Bf, dinv, b1, C, N);

    // layer 2: 64 -> 128
    sgemm_f(C, W2, N, 128, 64, A, Bf, dinv, nullptr, 0);
    scatter<128>(A, Bf, src, dst, E);
    finish<128>(Bf, dinv, b2, C, N);

    // layer 3: 128 -> 256
    sgemm_f(C, W3, N, 256, 128, A, Bf, dinv, nullptr, 0);
    scatter<256>(A, Bf, src, dst, E);
    finish<256>(Bf, dinv, b3, C, N);

    // segmented mean pool -> cat[:, catoff:catoff+256]
    pool_seg<<<NB, 256>>>(C, batch, N, cat, catoff);
}

extern "C" void kernel_launch(void* const* d_in, const int* in_sizes, int n_in,
                              void* d_out, int out_size)
{
    const float* p_x    = (const float*)d_in[0];
    const int*   p_ei   = (const int*)d_in[1];
    const int*   p_bat  = (const int*)d_in[2];
    const float* l_x    = (const float*)d_in[3];
    const int*   l_ei   = (const int*)d_in[4];
    const int*   l_bat  = (const int*)d_in[5];
    const float* p_W1 = (const float*)d_in[6],  *p_b1 = (const float*)d_in[7];
    const float* p_W2 = (const float*)d_in[8],  *p_b2 = (const float*)d_in[9];
    const float* p_W3 = (const float*)d_in[10], *p_b3 = (const float*)d_in[11];
    const float* l_W1 = (const float*)d_in[12], *l_b1 = (const float*)d_in[13];
    const float* l_W2 = (const float*)d_in[14], *l_b2 = (const float*)d_in[15];
    const float* l_W3 = (const float*)d_in[16], *l_b3 = (const float*)d_in[17];
    const float* fc1_W = (const float*)d_in[18], *fc1_b = (const float*)d_in[19];
    const float* fc2_W = (const float*)d_in[20], *fc2_b = (const float*)d_in[21];
    const float* out_W = (const float*)d_in[22], *out_b = (const float*)d_in[23];
    float* out = (float*)d_out;

    float *pA, *pB, *pC, *lA, *lB, *lC, *deg, *pdinv, *ldinv, *cat, *fc1, *fc2;
    cudaGetSymbolAddress((void**)&pA, g_pA);
    cudaGetSymbolAddress((void**)&pB, g_pB);
    cudaGetSymbolAddress((void**)&pC, g_pC);
    cudaGetSymbolAddress((void**)&lA, g_lA);
    cudaGetSymbolAddress((void**)&lB, g_lB);
    cudaGetSymbolAddress((void**)&lC, g_lC);
    cudaGetSymbolAddress((void**)&deg, g_deg);
    cudaGetSymbolAddress((void**)&pdinv, g_pdinv);
    cudaGetSymbolAddress((void**)&ldinv, g_ldinv);
    cudaGetSymbolAddress((void**)&cat, g_cat);
    cudaGetSymbolAddress((void**)&fc1, g_fc1);
    cudaGetSymbolAddress((void**)&fc2, g_fc2);

    // p branch: src = p_ei[0:E], dst = p_ei[E:2E]
    run_branch(p_x, 41, PN, PE, p_ei, p_ei + PE, p_bat,
               p_W1, p_b1, p_W2, p_b2, p_W3, p_b3,
               pA, pB, pC, deg, pdinv, cat, /*catoff=*/0);

    // l branch
    run_branch(l_x, 78, LN, LE, l_ei, l_ei + LE, l_bat,
               l_W1, l_b1, l_W2, l_b2, l_W3, l_b3,
               lA, lB, lC, deg, ldinv, cat, /*catoff=*/256);

    // MLP head
    sgemm_f(cat, fc1_W, NB, 1024, 512, fc1, nullptr, nullptr, fc1_b, 1);
    sgemm_f(fc1, fc2_W, NB, 512, 1024, fc2, nullptr, nullptr, fc2_b, 1);
    out_kernel<<<NB, 256>>>(fc2, out_W, out_b, out);
}

// round 12
// speedup vs baseline: 1.5356x; 1.2749x over previous
#include <cuda_runtime.h>
#include <math.h>

// Problem-fixed sizes
#define PN 200000
#define PE 800000
#define LN 100000
#define LE 400000
#define NB 512

// ---------------- scratch (static device globals; no allocation) ----------------
__device__ float g_pA[(size_t)PN * 256];
__device__ float g_pC[(size_t)PN * 256];
__device__ float g_lA[(size_t)LN * 256];
__device__ float g_lC[(size_t)LN * 256];
__device__ float g_dinv[PN];
__device__ int   g_cnt[PN];
__device__ int   g_rp[PN];
__device__ int   g_cursor[PN];
__device__ int   g_esrc[PE];
__device__ int   g_part[1024];
__device__ float g_cat[NB * 512];
__device__ float g_fc1[NB * 1024];
__device__ float g_fc2[NB * 512];

// ---------------- CSR build ----------------
__global__ void zero_i(int* p, int n) {
    int i = blockIdx.x * blockDim.x + threadIdx.x;
    if (i < n) p[i] = 0;
}
__global__ void hist_k(int* cnt, const int* __restrict__ dst, int E) {
    int i = blockIdx.x * blockDim.x + threadIdx.x;
    if (i < E) atomicAdd(&cnt[dst[i]], 1);
}
// exclusive scan, 1024-wide blocks
__global__ __launch_bounds__(1024) void scan1(const int* __restrict__ in, int* __restrict__ out,
                                              int* __restrict__ part, int n) {
    __shared__ int s[1024];
    int i = blockIdx.x * 1024 + threadIdx.x;
    int v = (i < n) ? in[i] : 0;
    s[threadIdx.x] = v;
    __syncthreads();
    for (int off = 1; off < 1024; off <<= 1) {
        int t = (threadIdx.x >= off) ? s[threadIdx.x - off] : 0;
        __syncthreads();
        s[threadIdx.x] += t;
        __syncthreads();
    }
    if (i < n) out[i] = s[threadIdx.x] - v;
    if (threadIdx.x == 1023) part[blockIdx.x] = s[1023];
}
__global__ __launch_bounds__(256) void scan2(int* part, int nb) {
    __shared__ int s[256];
    int v = (threadIdx.x < nb) ? part[threadIdx.x] : 0;
    s[threadIdx.x] = v;
    __syncthreads();
    for (int off = 1; off < 256; off <<= 1) {
        int t = (threadIdx.x >= off) ? s[threadIdx.x - off] : 0;
        __syncthreads();
        s[threadIdx.x] += t;
        __syncthreads();
    }
    if (threadIdx.x < nb) part[threadIdx.x] = s[threadIdx.x] - v;
}
__global__ __launch_bounds__(1024) void scan3(int* __restrict__ out, const int* __restrict__ part,
                                              int* __restrict__ cursor, int n) {
    int i = blockIdx.x * 1024 + threadIdx.x;
    if (i < n) {
        int v = out[i] + part[blockIdx.x];
        out[i] = v;
        cursor[i] = v;
    }
}
__global__ void bucket_fill(const int* __restrict__ src, const int* __restrict__ dst,
                            int* __restrict__ cursor, int* __restrict__ esrc, int E) {
    int i = blockIdx.x * blockDim.x + threadIdx.x;
    if (i < E) {
        int pos = atomicAdd(&cursor[dst[i]], 1);
        esrc[pos] = src[i];
    }
}
__global__ void dinv_k(float* dinv, const int* __restrict__ cnt, int n) {
    int i = blockIdx.x * blockDim.x + threadIdx.x;
    if (i < n) dinv[i] = rsqrtf(1.0f + (float)cnt[i]);
}

// ---------------- slow-path GEMM (odd K / small N: layer 1 only) ----------------
#define BM0 64
#define BN0 64
#define BK0 8
#define TM0 4
#define TN0 4

__global__ __launch_bounds__(256) void sgemm_kernel(
    const float* __restrict__ A, const float* __restrict__ Bm,
    int M, int N, int K,
    float* __restrict__ C0,
    const float* __restrict__ rowscale,
    const float* __restrict__ bias, int do_relu)
{
    __shared__ float As[BM0][BK0];
    __shared__ float Bs[BK0][BN0];
    int tid = threadIdx.x;
    int tx = tid % 16, ty = tid / 16;
    int row0 = blockIdx.y * BM0, col0 = blockIdx.x * BN0;

    float acc[TM0][TN0] = {};

    for (int kk = 0; kk < K; kk += BK0) {
        #pragma unroll
        for (int i = tid; i < BM0 * BK0; i += 256) {
            int r = i / BK0, c = i % BK0;
            int gr = row0 + r, gc = kk + c;
            As[r][c] = (gr < M && gc < K) ? A[(size_t)gr * K + gc] : 0.f;
        }
        #pragma unroll
        for (int i = tid; i < BK0 * BN0; i += 256) {
            int r = i / BN0, c = i % BN0;
            int gr = kk + r, gc = col0 + c;
            Bs[r][c] = (gr < K && gc < N) ? Bm[(size_t)gr * N + gc] : 0.f;
        }
        __syncthreads();
        #pragma unroll
        for (int k = 0; k < BK0; k++) {
            float a[TM0], b[TN0];
            #pragma unroll
            for (int i = 0; i < TM0; i++) a[i] = As[ty * TM0 + i][k];
            #pragma unroll
            for (int j = 0; j < TN0; j++) b[j] = Bs[k][tx * TN0 + j];
            #pragma unroll
            for (int i = 0; i < TM0; i++)
                #pragma unroll
                for (int j = 0; j < TN0; j++)
                    acc[i][j] = fmaf(a[i], b[j], acc[i][j]);
        }
        __syncthreads();
    }

    #pragma unroll
    for (int i = 0; i < TM0; i++) {
        int gr = row0 + ty * TM0 + i;
        if (gr >= M) continue;
        float rs = rowscale ? rowscale[gr] : 1.f;
        #pragma unroll
        for (int j = 0; j < TN0; j++) {
            int gc = col0 + tx * TN0 + j;
            if (gc >= N) continue;
            float v = acc[i][j];
            if (bias) v += bias[gc];
            v *= rs;
            if (do_relu) v = fmaxf(v, 0.f);
            C0[(size_t)gr * N + gc] = v;
        }
    }
}

// ---------------- fast GEMM: 128x128 tile, 8x8 microtile, float4 everywhere ----
template<int BM, int BN, int TM, int TN>
__global__ __launch_bounds__(256) void sgemm_fast(
    const float* __restrict__ A, const float* __restrict__ Bm,
    int M, int N, int K,
    float* __restrict__ C0,
    const float* __restrict__ rowscale,
    const float* __restrict__ bias, int do_relu)
{
    constexpr int BK = 8;
    constexpr int TX = BN / TN;
    __shared__ float As[BK][BM];
    __shared__ float Bs[BK][BN];
    const int tid = threadIdx.x;
    const int row0 = blockIdx.y * BM;
    const int col0 = blockIdx.x * BN;
    const int tx = tid % TX, ty = tid / TX;

    float acc[TM][TN];
    #pragma unroll
    for (int i = 0; i < TM; i++)
        #pragma unroll
        for (int j = 0; j < TN; j++) acc[i][j] = 0.f;

    for (int kk = 0; kk < K; kk += BK) {
        #pragma unroll
        for (int f = tid; f < BM * BK / 4; f += 256) {
            int m = f >> 1;
            int kq = (f & 1) * 4;
            int gr = row0 + m;
            float4 v = make_float4(0.f, 0.f, 0.f, 0.f);
            if (gr < M)
                v = *reinterpret_cast<const float4*>(&A[(size_t)gr * K + kk + kq]);
            As[kq + 0][m] = v.x;
            As[kq + 1][m] = v.y;
            As[kq + 2][m] = v.z;
            As[kq + 3][m] = v.w;
        }
        #pragma unroll
        for (int f = tid; f < BK * BN / 4; f += 256) {
            int k = f / (BN / 4);
            int nq = (f % (BN / 4)) * 4;
            float4 v = *reinterpret_cast<const float4*>(&Bm[(size_t)(kk + k) * N + col0 + nq]);
            *reinterpret_cast<float4*>(&Bs[k][nq]) = v;
        }
        __syncthreads();

        #pragma unroll
        for (int k = 0; k < BK; k++) {
            float a[TM], b[TN];
            #pragma unroll
            for (int i = 0; i < TM; i += 4)
                *reinterpret_cast<float4*>(&a[i]) =
                    *reinterpret_cast<const float4*>(&As[k][ty * TM + i]);
            #pragma unroll
            for (int j = 0; j < TN; j += 4)
                *reinterpret_cast<float4*>(&b[j]) =
                    *reinterpret_cast<const float4*>(&Bs[k][tx * TN + j]);
            #pragma unroll
            for (int i = 0; i < TM; i++)
                #pragma unroll
                for (int j = 0; j < TN; j++)
                    acc[i][j] = fmaf(a[i], b[j], acc[i][j]);
        }
        __syncthreads();
    }

    #pragma unroll
    for (int i = 0; i < TM; i++) {
        int gr = row0 + ty * TM + i;
        if (gr >= M) continue;
        float rs = rowscale ? rowscale[gr] : 1.f;
        float v[TN];
        #pragma unroll
        for (int j = 0; j < TN; j++) {
            int gc = col0 + tx * TN + j;
            float t = acc[i][j];
            if (bias) t += bias[gc];
            t *= rs;
            if (do_relu) t = fmaxf(t, 0.f);
            v[j] = t;
        }
        size_t base = (size_t)gr * N + col0 + tx * TN;
        #pragma unroll
        for (int j = 0; j < TN; j += 4)
            *reinterpret_cast<float4*>(&C0[base + j]) = *reinterpret_cast<float4*>(&v[j]);
    }
}

// ---------------- fused GCN gather: one warp per node --------------------------
// out[d] = relu( dinv[d] * ( h[d] + sum_{e in CSR row d} h[esrc[e]] ) + bias )
template <int F>
__global__ __launch_bounds__(256) void gcn_gather(
    const float* __restrict__ h, const int* __restrict__ rp, const int* __restrict__ cnt,
    const int* __restrict__ esrc, const float* __restrict__ dinv,
    const float* __restrict__ bias, float* __restrict__ out, int N)
{
    int node = (int)((blockIdx.x * blockDim.x + threadIdx.x) >> 5);
    if (node >= N) return;
    int lane = threadIdx.x & 31;
    constexpr int R = F / 32;  // floats per lane: 2, 4, or 8
    float acc[R];

    // self term
    {
        const float* p = h + (size_t)node * F;
        if constexpr (F == 64) {
            float2 v = *reinterpret_cast<const float2*>(p + lane * 2);
            acc[0] = v.x; acc[1] = v.y;
        } else if constexpr (F == 128) {
            float4 v = *reinterpret_cast<const float4*>(p + lane * 4);
            acc[0] = v.x; acc[1] = v.y; acc[2] = v.z; acc[3] = v.w;
        } else {
            float4 a = *reinterpret_cast<const float4*>(p + lane * 4);
            float4 b = *reinterpret_cast<const float4*>(p + 128 + lane * 4);
            acc[0] = a.x; acc[1] = a.y; acc[2] = a.z; acc[3] = a.w;
            acc[4] = b.x; acc[5] = b.y; acc[6] = b.z; acc[7] = b.w;
        }
    }

    int start = rp[node], len = cnt[node];
    for (int base = 0; base < len; base += 32) {
        int myidx = (base + lane < len) ? esrc[start + base + lane] : 0;
        int m = min(32, len - base);
        for (int j = 0; j < m; j++) {
            int s = __shfl_sync(0xffffffffu, myidx, j);
            const float* p = h + (size_t)s * F;
            if constexpr (F == 64) {
                float2 v = *reinterpret_cast<const float2*>(p + lane * 2);
                acc[0] += v.x; acc[1] += v.y;
            } else if constexpr (F == 128) {
                float4 v = *reinterpret_cast<const float4*>(p + lane * 4);
                acc[0] += v.x; acc[1] += v.y; acc[2] += v.z; acc[3] += v.w;
            } else {
                float4 a = *reinterpret_cast<const float4*>(p + lane * 4);
                float4 b = *reinterpret_cast<const float4*>(p + 128 + lane * 4);
                acc[0] += a.x; acc[1] += a.y; acc[2] += a.z; acc[3] += a.w;
                acc[4] += b.x; acc[5] += b.y; acc[6] += b.z; acc[7] += b.w;
            }
        }
    }

    float di = dinv[node];
    float* o = out + (size_t)node * F;
    if constexpr (F == 64) {
        float2 v;
        v.x = fmaxf(fmaf(acc[0], di, bias[lane * 2 + 0]), 0.f);
        v.y = fmaxf(fmaf(acc[1], di, bias[lane * 2 + 1]), 0.f);
        *reinterpret_cast<float2*>(o + lane * 2) = v;
    } else if constexpr (F == 128) {
        float4 v;
        v.x = fmaxf(fmaf(acc[0], di, bias[lane * 4 + 0]), 0.f);
        v.y = fmaxf(fmaf(acc[1], di, bias[lane * 4 + 1]), 0.f);
        v.z = fmaxf(fmaf(acc[2], di, bias[lane * 4 + 2]), 0.f);
        v.w = fmaxf(fmaf(acc[3], di, bias[lane * 4 + 3]), 0.f);
        *reinterpret_cast<float4*>(o + lane * 4) = v;
    } else {
        float4 a, b;
        a.x = fmaxf(fmaf(acc[0], di, bias[lane * 4 + 0]), 0.f);
        a.y = fmaxf(fmaf(acc[1], di, bias[lane * 4 + 1]), 0.f);
        a.z = fmaxf(fmaf(acc[2], di, bias[lane * 4 + 2]), 0.f);
        a.w = fmaxf(fmaf(acc[3], di, bias[lane * 4 + 3]), 0.f);
        b.x = fmaxf(fmaf(acc[4], di, bias[128 + lane * 4 + 0]), 0.f);
        b.y = fmaxf(fmaf(acc[5], di, bias[128 + lane * 4 + 1]), 0.f);
        b.z = fmaxf(fmaf(acc[6], di, bias[128 + lane * 4 + 2]), 0.f);
        b.w = fmaxf(fmaf(acc[7], di, bias[128 + lane * 4 + 3]), 0.f);
        *reinterpret_cast<float4*>(o + lane * 4) = a;
        *reinterpret_cast<float4*>(o + 128 + lane * 4) = b;
    }
}

// ---------------- segmented mean-pool (batch is sorted) ------------------------
__global__ void pool_seg(const float* __restrict__ x, const int* __restrict__ batch,
                         int N, float* __restrict__ cat, int off)
{
    int b = blockIdx.x;
    int l = 0, r = N;
    while (l < r) { int m = (l + r) >> 1; if (batch[m] < b) l = m + 1; else r = m; }
    int start = l;
    r = N;
    while (l < r) { int m = (l + r) >> 1; if (batch[m] < b + 1) l = m + 1; else r = m; }
    int end = l;
    int c = threadIdx.x;
    float s = 0.f;
    for (int i = start; i < end; i++)
        s += x[(size_t)i * 256 + c];
    float cnt = (float)(end - start);
    cat[b * 512 + off + c] = s / fmaxf(cnt, 1.f);
}

// ---------------- final linear head ----------------
__global__ void out_kernel(const float* __restrict__ X, const float* __restrict__ W,
                           const float* __restrict__ bias, float* __restrict__ out)
{
    int b = blockIdx.x;
    __shared__ float red[256];
    float s = 0.f;
    for (int k = threadIdx.x; k < 512; k += 256)
        s += X[b * 512 + k] * W[k];
    red[threadIdx.x] = s;
    __syncthreads();
    for (int off = 128; off > 0; off >>= 1) {
        if (threadIdx.x < off) red[threadIdx.x] += red[threadIdx.x + off];
        __syncthreads();
    }
    if (threadIdx.x == 0) out[b] = red[0] + bias[0];
}

// ---------------- host side ----------------
static inline void sgemm_slow(const float* A, const float* B, int M, int N, int K,
                              float* C0, const float* rs, const float* bias, int relu)
{
    dim3 grid((N + BN0 - 1) / BN0, (M + BM0 - 1) / BM0);
    sgemm_kernel<<<grid, 256>>>(A, B, M, N, K, C0, rs, bias, relu);
}

static inline void sgemm_f(const float* A, const float* B, int M, int N, int K,
                           float* C0, const float* rs, const float* bias, int relu)
{
    dim3 grid(N / 128, (M + 127) / 128);
    sgemm_fast<128, 128, 8, 8><<<grid, 256>>>(A, B, M, N, K, C0, rs, bias, relu);
}

template <int F>
static inline void gather(const float* h, const int* rp, const int* cnt, const int* esrc,
                          const float* dinv, const float* bias, float* out, int N)
{
    int blocks = (N * 32 + 255) / 256;
    gcn_gather<F><<<blocks, 256>>>(h, rp, cnt, esrc, dinv, bias, out, N);
}

static void run_branch(const float* x, int Fin, int N, int E,
                       const int* src, const int* dst, const int* batch,
                       const float* W1, const float* b1,
                       const float* W2, const float* b2,
                       const float* W3, const float* b3,
                       float* A, float* C,
                       int* cnt, int* rp, int* cursor, int* esrc, int* part, float* dinv,
                       float* cat, int catoff)
{
    // ---- CSR build (dst-keyed) + dinv ----
    zero_i<<<(N + 255) / 256, 256>>>(cnt, N);
    hist_k<<<(E + 255) / 256, 256>>>(cnt, dst, E);
    int nb = (N + 1023) / 1024;
    scan1<<<nb, 1024>>>(cnt, rp, part, N);
    scan2<<<1, 256>>>(part, nb);
    scan3<<<nb, 1024>>>(rp, part, cursor, N);
    bucket_fill<<<(E + 255) / 256, 256>>>(src, dst, cursor, esrc, E);
    dinv_k<<<(N + 255) / 256, 256>>>(dinv, cnt, N);

    // layer 1: Fin -> 64
    sgemm_slow(x, W1, N, 64, Fin, A, dinv, nullptr, 0);
    gather<64>(A, rp, cnt, esrc, dinv, b1, C, N);

    // layer 2: 64 -> 128
    sgemm_f(C, W2, N, 128, 64, A, dinv, nullptr, 0);
    gather<128>(A, rp, cnt, esrc, dinv, b2, C, N);

    // layer 3: 128 -> 256
    sgemm_f(C, W3, N, 256, 128, A, dinv, nullptr, 0);
    gather<256>(A, rp, cnt, esrc, dinv, b3, C, N);

    // segmented mean pool -> cat[:, catoff:catoff+256]
    pool_seg<<<NB, 256>>>(C, batch, N, cat, catoff);
}

extern "C" void kernel_launch(void* const* d_in, const int* in_sizes, int n_in,
                              void* d_out, int out_size)
{
    const float* p_x    = (const float*)d_in[0];
    const int*   p_ei   = (const int*)d_in[1];
    const int*   p_bat  = (const int*)d_in[2];
    const float* l_x    = (const float*)d_in[3];
    const int*   l_ei   = (const int*)d_in[4];
    const int*   l_bat  = (const int*)d_in[5];
    const float* p_W1 = (const float*)d_in[6],  *p_b1 = (const float*)d_in[7];
    const float* p_W2 = (const float*)d_in[8],  *p_b2 = (const float*)d_in[9];
    const float* p_W3 = (const float*)d_in[10], *p_b3 = (const float*)d_in[11];
    const float* l_W1 = (const float*)d_in[12], *l_b1 = (const float*)d_in[13];
    const float* l_W2 = (const float*)d_in[14], *l_b2 = (const float*)d_in[15];
    const float* l_W3 = (const float*)d_in[16], *l_b3 = (const float*)d_in[17];
    const float* fc1_W = (const float*)d_in[18], *fc1_b = (const float*)d_in[19];
    const float* fc2_W = (const float*)d_in[20], *fc2_b = (const float*)d_in[21];
    const float* out_W = (const float*)d_in[22], *out_b = (const float*)d_in[23];
    float* out = (float*)d_out;

    float *pA, *pC, *lA, *lC, *dinv, *cat, *fc1, *fc2;
    int *cnt, *rp, *cursor, *esrc, *part;
    cudaGetSymbolAddress((void**)&pA, g_pA);
    cudaGetSymbolAddress((void**)&pC, g_pC);
    cudaGetSymbolAddress((void**)&lA, g_lA);
    cudaGetSymbolAddress((void**)&lC, g_lC);
    cudaGetSymbolAddress((void**)&dinv, g_dinv);
    cudaGetSymbolAddress((void**)&cnt, g_cnt);
    cudaGetSymbolAddress((void**)&rp, g_rp);
    cudaGetSymbolAddress((void**)&cursor, g_cursor);
    cudaGetSymbolAddress((void**)&esrc, g_esrc);
    cudaGetSymbolAddress((void**)&part, g_part);
    cudaGetSymbolAddress((void**)&cat, g_cat);
    cudaGetSymbolAddress((void**)&fc1, g_fc1);
    cudaGetSymbolAddress((void**)&fc2, g_fc2);

    // p branch: src = p_ei[0:E], dst = p_ei[E:2E]
    run_branch(p_x, 41, PN, PE, p_ei, p_ei + PE, p_bat,
               p_W1, p_b1, p_W2, p_b2, p_W3, p_b3,
               pA, pC, cnt, rp, cursor, esrc, part, dinv, cat, /*catoff=*/0);

    // l branch (reuses the CSR scratch arrays sequentially)
    run_branch(l_x, 78, LN, LE, l_ei, l_ei + LE, l_bat,
               l_W1, l_b1, l_W2, l_b2, l_W3, l_b3,
               lA, lC, cnt, rp, cursor, esrc, part, dinv, cat, /*catoff=*/256);

    // MLP head
    sgemm_f(cat, fc1_W, NB, 1024, 512, fc1, nullptr, fc1_b, 1);
    sgemm_f(fc1, fc2_W, NB, 512, 1024, fc2, nullptr, fc2_b, 1);
    out_kernel<<<NB, 256>>>(fc2, out_W, out_b, out);
}

// round 14
// speedup vs baseline: 2.6888x; 1.7510x over previous
#include <cuda_runtime.h>
#include <math.h>
#include <stdint.h>

// Problem-fixed sizes
#define PN 200000
#define PE 800000
#define LN 100000
#define LE 400000
#define NB 512

// ---------------- scratch (static device globals; no allocation) ----------------
__device__ float g_pA[(size_t)PN * 256];
__device__ float g_pC[(size_t)PN * 256];
__device__ float g_lA[(size_t)LN * 256];
__device__ float g_lC[(size_t)LN * 256];
__device__ float g_dinv[PN];
__device__ int   g_cnt[PN];
__device__ int   g_rp[PN];
__device__ int   g_cursor[PN];
__device__ int   g_esrc[PE];
__device__ int   g_part[1024];
__device__ float g_cat[NB * 512];
__device__ float g_fc1[NB * 1024];
__device__ float g_fc2[NB * 512];

// ---------------- CSR build ----------------
__global__ void zero_i(int* p, int n) {
    int i = blockIdx.x * blockDim.x + threadIdx.x;
    if (i < n) p[i] = 0;
}
__global__ void hist_k(int* cnt, const int* __restrict__ dst, int E) {
    int i = blockIdx.x * blockDim.x + threadIdx.x;
    if (i < E) atomicAdd(&cnt[dst[i]], 1);
}
__global__ __launch_bounds__(1024) void scan1(const int* __restrict__ in, int* __restrict__ out,
                                              int* __restrict__ part, int n) {
    __shared__ int s[1024];
    int i = blockIdx.x * 1024 + threadIdx.x;
    int v = (i < n) ? in[i] : 0;
    s[threadIdx.x] = v;
    __syncthreads();
    for (int off = 1; off < 1024; off <<= 1) {
        int t = (threadIdx.x >= off) ? s[threadIdx.x - off] : 0;
        __syncthreads();
        s[threadIdx.x] += t;
        __syncthreads();
    }
    if (i < n) out[i] = s[threadIdx.x] - v;
    if (threadIdx.x == 1023) part[blockIdx.x] = s[1023];
}
__global__ __launch_bounds__(256) void scan2(int* part, int nb) {
    __shared__ int s[256];
    int v = (threadIdx.x < nb) ? part[threadIdx.x] : 0;
    s[threadIdx.x] = v;
    __syncthreads();
    for (int off = 1; off < 256; off <<= 1) {
        int t = (threadIdx.x >= off) ? s[threadIdx.x - off] : 0;
        __syncthreads();
        s[threadIdx.x] += t;
        __syncthreads();
    }
    if (threadIdx.x < nb) part[threadIdx.x] = s[threadIdx.x] - v;
}
__global__ __launch_bounds__(1024) void scan3(int* __restrict__ out, const int* __restrict__ part,
                                              int* __restrict__ cursor, int n) {
    int i = blockIdx.x * 1024 + threadIdx.x;
    if (i < n) {
        int v = out[i] + part[blockIdx.x];
        out[i] = v;
        cursor[i] = v;
    }
}
__global__ void bucket_fill(const int* __restrict__ src, const int* __restrict__ dst,
                            int* __restrict__ cursor, int* __restrict__ esrc, int E) {
    int i = blockIdx.x * blockDim.x + threadIdx.x;
    if (i < E) {
        int pos = atomicAdd(&cursor[dst[i]], 1);
        esrc[pos] = src[i];
    }
}
__global__ void dinv_k(float* dinv, const int* __restrict__ cnt, int n) {
    int i = blockIdx.x * blockDim.x + threadIdx.x;
    if (i < n) dinv[i] = rsqrtf(1.0f + (float)cnt[i]);
}

// ---------------- slow fp32 GEMM (layer 1: odd K, N=64) ------------------------
// epilogue: v = relu(acc + bias[col]); if (outscale) v *= outscale[row]
#define BM0 64
#define BN0 64
#define BK0 8
#define TM0 4
#define TN0 4

__global__ __launch_bounds__(256) void sgemm_slow_k(
    const float* __restrict__ A, const float* __restrict__ Bm,
    int M, int N, int K,
    float* __restrict__ C0,
    const float* __restrict__ outscale,
    const float* __restrict__ bias)
{
    __shared__ float As[BM0][BK0];
    __shared__ float Bs[BK0][BN0];
    int tid = threadIdx.x;
    int tx = tid % 16, ty = tid / 16;
    int row0 = blockIdx.y * BM0, col0 = blockIdx.x * BN0;

    float acc[TM0][TN0] = {};

    for (int kk = 0; kk < K; kk += BK0) {
        #pragma unroll
        for (int i = tid; i < BM0 * BK0; i += 256) {
            int r = i / BK0, c = i % BK0;
            int gr = row0 + r, gc = kk + c;
            As[r][c] = (gr < M && gc < K) ? A[(size_t)gr * K + gc] : 0.f;
        }
        #pragma unroll
        for (int i = tid; i < BK0 * BN0; i += 256) {
            int r = i / BN0, c = i % BN0;
            int gr = kk + r, gc = col0 + c;
            Bs[r][c] = (gr < K && gc < N) ? Bm[(size_t)gr * N + gc] : 0.f;
        }
        __syncthreads();
        #pragma unroll
        for (int k = 0; k < BK0; k++) {
            float a[TM0], b[TN0];
            #pragma unroll
            for (int i = 0; i < TM0; i++) a[i] = As[ty * TM0 + i][k];
            #pragma unroll
            for (int j = 0; j < TN0; j++) b[j] = Bs[k][tx * TN0 + j];
            #pragma unroll
            for (int i = 0; i < TM0; i++)
                #pragma unroll
                for (int j = 0; j < TN0; j++)
                    acc[i][j] = fmaf(a[i], b[j], acc[i][j]);
        }
        __syncthreads();
    }

    #pragma unroll
    for (int i = 0; i < TM0; i++) {
        int gr = row0 + ty * TM0 + i;
        if (gr >= M) continue;
        float os = outscale ? outscale[gr] : 1.f;
        #pragma unroll
        for (int j = 0; j < TN0; j++) {
            int gc = col0 + tx * TN0 + j;
            if (gc >= N) continue;
            float v = fmaxf(acc[i][j] + bias[gc], 0.f) * os;
            C0[(size_t)gr * N + gc] = v;
        }
    }
}

// ---------------- tf32 tensor-core GEMM ----------------------------------------
// C[M,N] = epi(A[M,K] @ B[K,N]); requires K%16==0, N%128==0; row guard on M.
// epi: v = acc + bias[col]; if relu v=max(v,0); if outscale v*=outscale[row]
__device__ __forceinline__ float to_tf32(float x) {
    float r;
    asm("cvt.rna.tf32.f32 %0, %1;" : "=f"(r) : "f"(x));
    return r;
}

__global__ __launch_bounds__(256) void sgemm_tf32(
    const float* __restrict__ A, const float* __restrict__ Bm,
    int M, int N, int K,
    float* __restrict__ C,
    const float* __restrict__ outscale,
    const float* __restrict__ bias, int do_relu)
{
    __shared__ float As[128][20];   // stride 20: conflict-free, rows 16B-aligned
    __shared__ float Bs[16][132];   // stride 132: conflict-free, rows 16B-aligned
    const int tid = threadIdx.x;
    const int lane = tid & 31;
    const int warp = tid >> 5;
    const int wm = warp & 1;        // 2 warps along M
    const int wn = warp >> 1;       // 4 warps along N
    const int row0 = blockIdx.y * 128;
    const int col0 = blockIdx.x * 128;

    float c[4][4][4];
    #pragma unroll
    for (int mt = 0; mt < 4; mt++)
        #pragma unroll
        for (int nt = 0; nt < 4; nt++)
            #pragma unroll
            for (int r = 0; r < 4; r++) c[mt][nt][r] = 0.f;

    const int qr = lane >> 2;   // 0..7
    const int qc = lane & 3;    // 0..3

    for (int kk = 0; kk < K; kk += 16) {
        // A tile 128x16, float4 loads, tf32-round into smem
        #pragma unroll
        for (int f = tid; f < 512; f += 256) {
            int m = f >> 2;
            int kq = (f & 3) * 4;
            int gr = row0 + m;
            float4 v = make_float4(0.f, 0.f, 0.f, 0.f);
            if (gr < M)
                v = *reinterpret_cast<const float4*>(&A[(size_t)gr * K + kk + kq]);
            As[m][kq + 0] = to_tf32(v.x);
            As[m][kq + 1] = to_tf32(v.y);
            As[m][kq + 2] = to_tf32(v.z);
            As[m][kq + 3] = to_tf32(v.w);
        }
        // B tile 16x128
        #pragma unroll
        for (int f = tid; f < 512; f += 256) {
            int k = f >> 5;
            int nq = (f & 31) * 4;
            float4 v = *reinterpret_cast<const float4*>(&Bm[(size_t)(kk + k) * N + col0 + nq]);
            Bs[k][nq + 0] = to_tf32(v.x);
            Bs[k][nq + 1] = to_tf32(v.y);
            Bs[k][nq + 2] = to_tf32(v.z);
            Bs[k][nq + 3] = to_tf32(v.w);
        }
        __syncthreads();

        #pragma unroll
        for (int ks = 0; ks < 16; ks += 8) {
            uint32_t af[4][4];
            #pragma unroll
            for (int mt = 0; mt < 4; mt++) {
                int r = wm * 64 + mt * 16 + qr;
                af[mt][0] = __float_as_uint(As[r][ks + qc]);
                af[mt][1] = __float_as_uint(As[r + 8][ks + qc]);
                af[mt][2] = __float_as_uint(As[r][ks + qc + 4]);
                af[mt][3] = __float_as_uint(As[r + 8][ks + qc + 4]);
            }
            uint32_t bf[4][2];
            #pragma unroll
            for (int nt = 0; nt < 4; nt++) {
                int cb = wn * 32 + nt * 8 + qr;
                bf[nt][0] = __float_as_uint(Bs[ks + qc][cb]);
                bf[nt][1] = __float_as_uint(Bs[ks + 4 + qc][cb]);
            }
            #pragma unroll
            for (int mt = 0; mt < 4; mt++)
                #pragma unroll
                for (int nt = 0; nt < 4; nt++) {
                    asm volatile(
                        "mma.sync.aligned.m16n8k8.row.col.f32.tf32.tf32.f32 "
                        "{%0,%1,%2,%3}, {%4,%5,%6,%7}, {%8,%9}, {%0,%1,%2,%3};"
                        : "+f"(c[mt][nt][0]), "+f"(c[mt][nt][1]),
                          "+f"(c[mt][nt][2]), "+f"(c[mt][nt][3])
                        : "r"(af[mt][0]), "r"(af[mt][1]), "r"(af[mt][2]), "r"(af[mt][3]),
                          "r"(bf[nt][0]), "r"(bf[nt][1]));
                }
        }
        __syncthreads();
    }

    // epilogue
    #pragma unroll
    for (int mt = 0; mt < 4; mt++) {
        #pragma unroll
        for (int nt = 0; nt < 4; nt++) {
            int r = row0 + wm * 64 + mt * 16 + qr;
            int cc = col0 + wn * 32 + nt * 8 + 2 * qc;
            if (r < M) {
                float os = outscale ? outscale[r] : 1.f;
                float v0 = c[mt][nt][0] + bias[cc];
                float v1 = c[mt][nt][1] + bias[cc + 1];
                if (do_relu) { v0 = fmaxf(v0, 0.f); v1 = fmaxf(v1, 0.f); }
                float2 q = make_float2(v0 * os, v1 * os);
                *reinterpret_cast<float2*>(&C[(size_t)r * N + cc]) = q;
            }
            int r2 = r + 8;
            if (r2 < M) {
                float os = outscale ? outscale[r2] : 1.f;
                float v0 = c[mt][nt][2] + bias[cc];
                float v1 = c[mt][nt][3] + bias[cc + 1];
                if (do_relu) { v0 = fmaxf(v0, 0.f); v1 = fmaxf(v1, 0.f); }
                float2 q = make_float2(v0 * os, v1 * os);
                *reinterpret_cast<float2*>(&C[(size_t)r2 * N + cc]) = q;
            }
        }
    }
}

// ---------------- input gather (layer 1): raw features, per-src dinv scale -----
// out[d] = dinv[d] * ( dinv[d]*x[d] + sum_e dinv[s_e]*x[s_e] )   [N x FIN]
template <int FIN>
__global__ __launch_bounds__(256) void gather_in(
    const float* __restrict__ x, const int* __restrict__ rp, const int* __restrict__ cnt,
    const int* __restrict__ esrc, const float* __restrict__ dinv,
    float* __restrict__ out, int N)
{
    int node = (int)((blockIdx.x * blockDim.x + threadIdx.x) >> 5);
    if (node >= N) return;
    int lane = threadIdx.x & 31;
    constexpr int R = (FIN + 31) / 32;
    float acc[R];
    float dn = dinv[node];

    #pragma unroll
    for (int j = 0; j < R; j++) {
        int cc = lane + 32 * j;
        acc[j] = (cc < FIN) ? dn * x[(size_t)node * FIN + cc] : 0.f;
    }

    int start = rp[node], len = cnt[node];
    for (int base = 0; base < len; base += 32) {
        int valid = (base + lane < len);
        int myidx = valid ? esrc[start + base + lane] : 0;
        float myds = valid ? dinv[myidx] : 0.f;
        int m = min(32, len - base);
        for (int j = 0; j < m; j++) {
            int s = __shfl_sync(0xffffffffu, myidx, j);
            float ds = __shfl_sync(0xffffffffu, myds, j);
            const float* p = x + (size_t)s * FIN;
            #pragma unroll
            for (int q = 0; q < R; q++) {
                int cc = lane + 32 * q;
                if (cc < FIN) acc[q] = fmaf(ds, p[cc], acc[q]);
            }
        }
    }

    #pragma unroll
    for (int j = 0; j < R; j++) {
        int cc = lane + 32 * j;
        if (cc < FIN) out[(size_t)node * FIN + cc] = acc[j] * dn;
    }
}

// ---------------- hidden gather (layers 2/3): input pre-scaled by dinv ---------
// out[d] = dinv[d] * ( y[d] + sum_e y[s_e] )
template <int F>
__global__ __launch_bounds__(256) void gather_mid(
    const float* __restrict__ h, const int* __restrict__ rp, const int* __restrict__ cnt,
    const int* __restrict__ esrc, const float* __restrict__ dinv,
    float* __restrict__ out, int N)
{
    int node = (int)((blockIdx.x * blockDim.x + threadIdx.x) >> 5);
    if (node >= N) return;
    int lane = threadIdx.x & 31;
    constexpr int R = F / 32;   // 2 for 64, 4 for 128
    float acc[R];

    {
        const float* p = h + (size_t)node * F;
        if constexpr (F == 64) {
            float2 v = *reinterpret_cast<const float2*>(p + lane * 2);
            acc[0] = v.x; acc[1] = v.y;
        } else {
            float4 v = *reinterpret_cast<const float4*>(p + lane * 4);
            acc[0] = v.x; acc[1] = v.y; acc[2] = v.z; acc[3] = v.w;
        }
    }

    int start = rp[node], len = cnt[node];
    for (int base = 0; base < len; base += 32) {
        int myidx = (base + lane < len) ? esrc[start + base + lane] : 0;
        int m = min(32, len - base);
        for (int j = 0; j < m; j++) {
            int s = __shfl_sync(0xffffffffu, myidx, j);
            const float* p = h + (size_t)s * F;
            if constexpr (F == 64) {
                float2 v = *reinterpret_cast<const float2*>(p + lane * 2);
                acc[0] += v.x; acc[1] += v.y;
            } else {
                float4 v = *reinterpret_cast<const float4*>(p + lane * 4);
                acc[0] += v.x; acc[1] += v.y; acc[2] += v.z; acc[3] += v.w;
            }
        }
    }

    float di = dinv[node];
    float* o = out + (size_t)node * F;
    if constexpr (F == 64) {
        float2 v = make_float2(acc[0] * di, acc[1] * di);
        *reinterpret_cast<float2*>(o + lane * 2) = v;
    } else {
        float4 v = make_float4(acc[0] * di, acc[1] * di, acc[2] * di, acc[3] * di);
        *reinterpret_cast<float4*>(o + lane * 4) = v;
    }
}

// ---------------- segmented mean-pool (batch is sorted) ------------------------
__global__ void pool_seg(const float* __restrict__ x, const int* __restrict__ batch,
                         int N, float* __restrict__ cat, int off)
{
    int b = blockIdx.x;
    int l = 0, r = N;
    while (l < r) { int m = (l + r) >> 1; if (batch[m] < b) l = m + 1; else r = m; }
    int start = l;
    r = N;
    while (l < r) { int m = (l + r) >> 1; if (batch[m] < b + 1) l = m + 1; else r = m; }
    int end = l;
    int c = threadIdx.x;
    float s = 0.f;
    for (int i = start; i < end; i++)
        s += x[(size_t)i * 256 + c];
    float cnt = (float)(end - start);
    cat[b * 512 + off + c] = s / fmaxf(cnt, 1.f);
}

// ---------------- final linear head ----------------
__global__ void out_kernel(const float* __restrict__ X, const float* __restrict__ W,
                           const float* __restrict__ bias, float* __restrict__ out)
{
    int b = blockIdx.x;
    __shared__ float red[256];
    float s = 0.f;
    for (int k = threadIdx.x; k < 512; k += 256)
        s += X[b * 512 + k] * W[k];
    red[threadIdx.x] = s;
    __syncthreads();
    for (int off = 128; off > 0; off >>= 1) {
        if (threadIdx.x < off) red[threadIdx.x] += red[threadIdx.x + off];
        __syncthreads();
    }
    if (threadIdx.x == 0) out[b] = red[0] + bias[0];
}

// ---------------- host side ----------------
static inline void gemm_slow(const float* A, const float* B, int M, int N, int K,
                             float* C0, const float* os, const float* bias)
{
    dim3 grid((N + BN0 - 1) / BN0, (M + BM0 - 1) / BM0);
    sgemm_slow_k<<<grid, 256>>>(A, B, M, N, K, C0, os, bias);
}
static inline void gemm_tc(const float* A, const float* B, int M, int N, int K,
                           float* C0, const float* os, const float* bias, int relu)
{
    dim3 grid(N / 128, (M + 127) / 128);
    sgemm_tf32<<<grid, 256>>>(A, B, M, N, K, C0, os, bias, relu);
}

template <int FIN>
static void run_branch(const float* x, int N, int E,
                       const int* src, const int* dst, const int* batch,
                       const float* W1, const float* b1,
                       const float* W2, const float* b2,
                       const float* W3, const float* b3,
                       float* A, float* C,
                       int* cnt, int* rp, int* cursor, int* esrc, int* part, float* dinv,
                       float* cat, int catoff)
{
    // CSR build (dst-keyed) + dinv
    zero_i<<<(N + 255) / 256, 256>>>(cnt, N);
    hist_k<<<(E + 255) / 256, 256>>>(cnt, dst, E);
    int nb = (N + 1023) / 1024;
    scan1<<<nb, 1024>>>(cnt, rp, part, N);
    scan2<<<1, 256>>>(part, nb);
    scan3<<<nb, 1024>>>(rp, part, cursor, N);
    bucket_fill<<<(E + 255) / 256, 256>>>(src, dst, cursor, esrc, E);
    dinv_k<<<(N + 255) / 256, 256>>>(dinv, cnt, N);

    int gblocks = (N * 32 + 255) / 256;

    // layer 1: gather raw x (FIN cols), then GEMM FIN->64 (fp32 SIMT)
    gather_in<FIN><<<gblocks, 256>>>(x, rp, cnt, esrc, dinv, A, N);
    gemm_slow(A, W1, N, 64, FIN, C, /*outscale=*/dinv, b1);   // C = dinv*relu(.)

    // layer 2: gather (64), GEMM 64->128 (tf32)
    gather_mid<64><<<gblocks, 256>>>(C, rp, cnt, esrc, dinv, A, N);
    gemm_tc(A, W2, N, 128, 64, C, /*outscale=*/dinv, b2, 1);  // C = dinv*relu(.)

    // layer 3: gather (128), GEMM 128->256 (tf32), plain relu output
    gather_mid<128><<<gblocks, 256>>>(C, rp, cnt, esrc, dinv, A, N);
    gemm_tc(A, W3, N, 256, 128, C, /*outscale=*/nullptr, b3, 1);

    // segmented mean pool -> cat[:, catoff:catoff+256]
    pool_seg<<<NB, 256>>>(C, batch, N, cat, catoff);
}

extern "C" void kernel_launch(void* const* d_in, const int* in_sizes, int n_in,
                              void* d_out, int out_size)
{
    const float* p_x    = (const float*)d_in[0];
    const int*   p_ei   = (const int*)d_in[1];
    const int*   p_bat  = (const int*)d_in[2];
    const float* l_x    = (const float*)d_in[3];
    const int*   l_ei   = (const int*)d_in[4];
    const int*   l_bat  = (const int*)d_in[5];
    const float* p_W1 = (const float*)d_in[6],  *p_b1 = (const float*)d_in[7];
    const float* p_W2 = (const float*)d_in[8],  *p_b2 = (const float*)d_in[9];
    const float* p_W3 = (const float*)d_in[10], *p_b3 = (const float*)d_in[11];
    const float* l_W1 = (const float*)d_in[12], *l_b1 = (const float*)d_in[13];
    const float* l_W2 = (const float*)d_in[14], *l_b2 = (const float*)d_in[15];
    const float* l_W3 = (const float*)d_in[16], *l_b3 = (const float*)d_in[17];
    const float* fc1_W = (const float*)d_in[18], *fc1_b = (const float*)d_in[19];
    const float* fc2_W = (const float*)d_in[20], *fc2_b = (const float*)d_in[21];
    const float* out_W = (const float*)d_in[22], *out_b = (const float*)d_in[23];
    float* out = (float*)d_out;

    float *pA, *pC, *lA, *lC, *dinv, *cat, *fc1, *fc2;
    int *cnt, *rp, *cursor, *esrc, *part;
    cudaGetSymbolAddress((void**)&pA, g_pA);
    cudaGetSymbolAddress((void**)&pC, g_pC);
    cudaGetSymbolAddress((void**)&lA, g_lA);
    cudaGetSymbolAddress((void**)&lC, g_lC);
    cudaGetSymbolAddress((void**)&dinv, g_dinv);
    cudaGetSymbolAddress((void**)&cnt, g_cnt);
    cudaGetSymbolAddress((void**)&rp, g_rp);
    cudaGetSymbolAddress((void**)&cursor, g_cursor);
    cudaGetSymbolAddress((void**)&esrc, g_esrc);
    cudaGetSymbolAddress((void**)&part, g_part);
    cudaGetSymbolAddress((void**)&cat, g_cat);
    cudaGetSymbolAddress((void**)&fc1, g_fc1);
    cudaGetSymbolAddress((void**)&fc2, g_fc2);

    // p branch: src = p_ei[0:E], dst = p_ei[E:2E]
    run_branch<41>(p_x, PN, PE, p_ei, p_ei + PE, p_bat,
                   p_W1, p_b1, p_W2, p_b2, p_W3, p_b3,
                   pA, pC, cnt, rp, cursor, esrc, part, dinv, cat, 0);

    // l branch (reuses CSR scratch sequentially)
    run_branch<78>(l_x, LN, LE, l_ei, l_ei + LE, l_bat,
                   l_W1, l_b1, l_W2, l_b2, l_W3, l_b3,
                   lA, lC, cnt, rp, cursor, esrc, part, dinv, cat, 256);

    // MLP head (tf32)
    gemm_tc(cat, fc1_W, NB, 1024, 512, fc1, nullptr, fc1_b, 1);
    gemm_tc(fc1, fc2_W, NB, 512, 1024, fc2, nullptr, fc2_b, 1);
    out_kernel<<<NB, 256>>>(fc2, out_W, out_b, out);
}

// round 15
// speedup vs baseline: 2.8317x; 1.0532x over previous
#include <cuda_runtime.h>
#include <math.h>
#include <stdint.h>

// Problem-fixed sizes
#define PN 200000
#define PE 800000
#define LN 100000
#define LE 400000
#define NB 512

// ---------------- scratch (static device globals; no allocation) ----------------
__device__ float g_pA[(size_t)PN * 256];
__device__ float g_pC[(size_t)PN * 256];
__device__ float g_lA[(size_t)LN * 256];
__device__ float g_lC[(size_t)LN * 256];
__device__ float g_dinv[PN];
__device__ int   g_cnt[PN];
__device__ int   g_rp[PN];
__device__ int   g_cursor[PN];
__device__ int   g_esrc[PE];
__device__ int   g_part[1024];
__device__ float g_cat[NB * 512];
__device__ float g_fc1[NB * 1024];
__device__ float g_fc2[NB * 512];

// ---------------- CSR build ----------------
__global__ void zero_i(int* p, int n) {
    int i = blockIdx.x * blockDim.x + threadIdx.x;
    if (i < n) p[i] = 0;
}
__global__ void hist_k(int* cnt, const int* __restrict__ dst, int E) {
    int i = blockIdx.x * blockDim.x + threadIdx.x;
    if (i < E) atomicAdd(&cnt[dst[i]], 1);
}
__global__ __launch_bounds__(1024) void scan1(const int* __restrict__ in, int* __restrict__ out,
                                              int* __restrict__ part, int n) {
    __shared__ int s[1024];
    int i = blockIdx.x * 1024 + threadIdx.x;
    int v = (i < n) ? in[i] : 0;
    s[threadIdx.x] = v;
    __syncthreads();
    for (int off = 1; off < 1024; off <<= 1) {
        int t = (threadIdx.x >= off) ? s[threadIdx.x - off] : 0;
        __syncthreads();
        s[threadIdx.x] += t;
        __syncthreads();
    }
    if (i < n) out[i] = s[threadIdx.x] - v;
    if (threadIdx.x == 1023) part[blockIdx.x] = s[1023];
}
__global__ __launch_bounds__(256) void scan2(int* part, int nb) {
    __shared__ int s[256];
    int v = (threadIdx.x < nb) ? part[threadIdx.x] : 0;
    s[threadIdx.x] = v;
    __syncthreads();
    for (int off = 1; off < 256; off <<= 1) {
        int t = (threadIdx.x >= off) ? s[threadIdx.x - off] : 0;
        __syncthreads();
        s[threadIdx.x] += t;
        __syncthreads();
    }
    if (threadIdx.x < nb) part[threadIdx.x] = s[threadIdx.x] - v;
}
__global__ __launch_bounds__(1024) void scan3(int* __restrict__ out, const int* __restrict__ part,
                                              int* __restrict__ cursor, int n) {
    int i = blockIdx.x * 1024 + threadIdx.x;
    if (i < n) {
        int v = out[i] + part[blockIdx.x];
        out[i] = v;
        cursor[i] = v;
    }
}
__global__ void bucket_fill(const int* __restrict__ src, const int* __restrict__ dst,
                            int* __restrict__ cursor, int* __restrict__ esrc, int E) {
    int i = blockIdx.x * blockDim.x + threadIdx.x;
    if (i < E) {
        int pos = atomicAdd(&cursor[dst[i]], 1);
        esrc[pos] = src[i];
    }
}
__global__ void dinv_k(float* dinv, const int* __restrict__ cnt, int n) {
    int i = blockIdx.x * blockDim.x + threadIdx.x;
    if (i < n) dinv[i] = rsqrtf(1.0f + (float)cnt[i]);
}

// ---------------- tf32 helpers ----------------
__device__ __forceinline__ float to_tf32(float x) {
    float r;
    asm("cvt.rna.tf32.f32 %0, %1;" : "=f"(r) : "f"(x));
    return r;
}

// ---------------- tf32 tensor-core GEMM, BN=128 --------------------------------
// C[M,N] = epi(A[M,K] @ B[K,N]); K%16==0, N%128==0; row guard on M.
// epi: v = acc + bias[col]; if relu v=max(v,0); if outscale v*=outscale[row]
__global__ __launch_bounds__(256) void sgemm_tf32(
    const float* __restrict__ A, const float* __restrict__ Bm,
    int M, int N, int K,
    float* __restrict__ C,
    const float* __restrict__ outscale,
    const float* __restrict__ bias, int do_relu)
{
    __shared__ float As[128][20];
    __shared__ float Bs[16][132];
    const int tid = threadIdx.x;
    const int lane = tid & 31;
    const int warp = tid >> 5;
    const int wm = warp & 1;
    const int wn = warp >> 1;
    const int row0 = blockIdx.y * 128;
    const int col0 = blockIdx.x * 128;

    float c[4][4][4];
    #pragma unroll
    for (int mt = 0; mt < 4; mt++)
        #pragma unroll
        for (int nt = 0; nt < 4; nt++)
            #pragma unroll
            for (int r = 0; r < 4; r++) c[mt][nt][r] = 0.f;

    const int qr = lane >> 2;
    const int qc = lane & 3;

    for (int kk = 0; kk < K; kk += 16) {
        #pragma unroll
        for (int f = tid; f < 512; f += 256) {
            int m = f >> 2;
            int kq = (f & 3) * 4;
            int gr = row0 + m;
            float4 v = make_float4(0.f, 0.f, 0.f, 0.f);
            if (gr < M)
                v = *reinterpret_cast<const float4*>(&A[(size_t)gr * K + kk + kq]);
            As[m][kq + 0] = to_tf32(v.x);
            As[m][kq + 1] = to_tf32(v.y);
            As[m][kq + 2] = to_tf32(v.z);
            As[m][kq + 3] = to_tf32(v.w);
        }
        #pragma unroll
        for (int f = tid; f < 512; f += 256) {
            int k = f >> 5;
            int nq = (f & 31) * 4;
            float4 v = *reinterpret_cast<const float4*>(&Bm[(size_t)(kk + k) * N + col0 + nq]);
            Bs[k][nq + 0] = to_tf32(v.x);
            Bs[k][nq + 1] = to_tf32(v.y);
            Bs[k][nq + 2] = to_tf32(v.z);
            Bs[k][nq + 3] = to_tf32(v.w);
        }
        __syncthreads();

        #pragma unroll
        for (int ks = 0; ks < 16; ks += 8) {
            uint32_t af[4][4];
            #pragma unroll
            for (int mt = 0; mt < 4; mt++) {
                int r = wm * 64 + mt * 16 + qr;
                af[mt][0] = __float_as_uint(As[r][ks + qc]);
                af[mt][1] = __float_as_uint(As[r + 8][ks + qc]);
                af[mt][2] = __float_as_uint(As[r][ks + qc + 4]);
                af[mt][3] = __float_as_uint(As[r + 8][ks + qc + 4]);
            }
            uint32_t bf[4][2];
            #pragma unroll
            for (int nt = 0; nt < 4; nt++) {
                int cb = wn * 32 + nt * 8 + qr;
                bf[nt][0] = __float_as_uint(Bs[ks + qc][cb]);
                bf[nt][1] = __float_as_uint(Bs[ks + 4 + qc][cb]);
            }
            #pragma unroll
            for (int mt = 0; mt < 4; mt++)
                #pragma unroll
                for (int nt = 0; nt < 4; nt++) {
                    asm volatile(
                        "mma.sync.aligned.m16n8k8.row.col.f32.tf32.tf32.f32 "
                        "{%0,%1,%2,%3}, {%4,%5,%6,%7}, {%8,%9}, {%0,%1,%2,%3};"
                        : "+f"(c[mt][nt][0]), "+f"(c[mt][nt][1]),
                          "+f"(c[mt][nt][2]), "+f"(c[mt][nt][3])
                        : "r"(af[mt][0]), "r"(af[mt][1]), "r"(af[mt][2]), "r"(af[mt][3]),
                          "r"(bf[nt][0]), "r"(bf[nt][1]));
                }
        }
        __syncthreads();
    }

    #pragma unroll
    for (int mt = 0; mt < 4; mt++) {
        #pragma unroll
        for (int nt = 0; nt < 4; nt++) {
            int r = row0 + wm * 64 + mt * 16 + qr;
            int cc = col0 + wn * 32 + nt * 8 + 2 * qc;
            if (r < M) {
                float os = outscale ? outscale[r] : 1.f;
                float v0 = c[mt][nt][0] + bias[cc];
                float v1 = c[mt][nt][1] + bias[cc + 1];
                if (do_relu) { v0 = fmaxf(v0, 0.f); v1 = fmaxf(v1, 0.f); }
                *reinterpret_cast<float2*>(&C[(size_t)r * N + cc]) = make_float2(v0 * os, v1 * os);
            }
            int r2 = r + 8;
            if (r2 < M) {
                float os = outscale ? outscale[r2] : 1.f;
                float v0 = c[mt][nt][2] + bias[cc];
                float v1 = c[mt][nt][3] + bias[cc + 1];
                if (do_relu) { v0 = fmaxf(v0, 0.f); v1 = fmaxf(v1, 0.f); }
                *reinterpret_cast<float2*>(&C[(size_t)r2 * N + cc]) = make_float2(v0 * os, v1 * os);
            }
        }
    }
}

// ---------------- tf32 GEMM, BN=64 (layer 1) -----------------------------------
// A is [M x KP] (padded, KP%16==0, zero tail); B is [Kact x 64] with row guard.
// Warp layout: 2 along M (64 rows) x 4 along N (16 cols). Warp tile 64x16.
// epi: v = relu(acc + bias[col]) * outscale[row]
template<int KP>
__global__ __launch_bounds__(256) void sgemm_tf32_n64(
    const float* __restrict__ A, const float* __restrict__ Bm,
    int M, int Kact,
    float* __restrict__ C,
    const float* __restrict__ outscale,
    const float* __restrict__ bias)
{
    constexpr int AS = KP + 4;        // (KP+4) % 32 == 20 for KP=48,80 -> conflict-free
    __shared__ float As[128][AS];
    __shared__ float Bs[16][68];
    const int tid = threadIdx.x;
    const int lane = tid & 31;
    const int warp = tid >> 5;
    const int wm = warp & 1;          // 2 along M
    const int wn = warp >> 1;         // 4 along N (16 cols each)
    const int row0 = blockIdx.y * 128;

    float c[4][2][4];
    #pragma unroll
    for (int mt = 0; mt < 4; mt++)
        #pragma unroll
        for (int nt = 0; nt < 2; nt++)
            #pragma unroll
            for (int r = 0; r < 4; r++) c[mt][nt][r] = 0.f;

    const int qr = lane >> 2;
    const int qc = lane & 3;

    // A tile: 128 x KP, loaded once (KP <= 80)
    #pragma unroll
    for (int f = tid; f < 128 * KP / 4; f += 256) {
        int m = f / (KP / 4);
        int kq = (f % (KP / 4)) * 4;
        int gr = row0 + m;
        float4 v = make_float4(0.f, 0.f, 0.f, 0.f);
        if (gr < M)
            v = *reinterpret_cast<const float4*>(&A[(size_t)gr * KP + kq]);
        As[m][kq + 0] = to_tf32(v.x);
        As[m][kq + 1] = to_tf32(v.y);
        As[m][kq + 2] = to_tf32(v.z);
        As[m][kq + 3] = to_tf32(v.w);
    }

    for (int kk = 0; kk < KP; kk += 16) {
        // B tile 16 x 64, row-guarded against Kact
        #pragma unroll
        for (int f = tid; f < 256; f += 256) {
            int k = f >> 4;
            int nq = (f & 15) * 4;
            int gk = kk + k;
            float4 v = make_float4(0.f, 0.f, 0.f, 0.f);
            if (gk < Kact)
                v = *reinterpret_cast<const float4*>(&Bm[(size_t)gk * 64 + nq]);
            Bs[k][nq + 0] = to_tf32(v.x);
            Bs[k][nq + 1] = to_tf32(v.y);
            Bs[k][nq + 2] = to_tf32(v.z);
            Bs[k][nq + 3] = to_tf32(v.w);
        }
        __syncthreads();

        #pragma unroll
        for (int ks = 0; ks < 16; ks += 8) {
            uint32_t af[4][4];
            #pragma unroll
            for (int mt = 0; mt < 4; mt++) {
                int r = wm * 64 + mt * 16 + qr;
                af[mt][0] = __float_as_uint(As[r][kk + ks + qc]);
                af[mt][1] = __float_as_uint(As[r + 8][kk + ks + qc]);
                af[mt][2] = __float_as_uint(As[r][kk + ks + qc + 4]);
                af[mt][3] = __float_as_uint(As[r + 8][kk + ks + qc + 4]);
            }
            uint32_t bf[2][2];
            #pragma unroll
            for (int nt = 0; nt < 2; nt++) {
                int cb = wn * 16 + nt * 8 + qr;
                bf[nt][0] = __float_as_uint(Bs[ks + qc][cb]);
                bf[nt][1] = __float_as_uint(Bs[ks + 4 + qc][cb]);
            }
            #pragma unroll
            for (int mt = 0; mt < 4; mt++)
                #pragma unroll
                for (int nt = 0; nt < 2; nt++) {
                    asm volatile(
                        "mma.sync.aligned.m16n8k8.row.col.f32.tf32.tf32.f32 "
                        "{%0,%1,%2,%3}, {%4,%5,%6,%7}, {%8,%9}, {%0,%1,%2,%3};"
                        : "+f"(c[mt][nt][0]), "+f"(c[mt][nt][1]),
                          "+f"(c[mt][nt][2]), "+f"(c[mt][nt][3])
                        : "r"(af[mt][0]), "r"(af[mt][1]), "r"(af[mt][2]), "r"(af[mt][3]),
                          "r"(bf[nt][0]), "r"(bf[nt][1]));
                }
        }
        __syncthreads();
    }

    #pragma unroll
    for (int mt = 0; mt < 4; mt++) {
        #pragma unroll
        for (int nt = 0; nt < 2; nt++) {
            int r = row0 + wm * 64 + mt * 16 + qr;
            int cc = wn * 16 + nt * 8 + 2 * qc;
            if (r < M) {
                float os = outscale[r];
                float v0 = fmaxf(c[mt][nt][0] + bias[cc], 0.f);
                float v1 = fmaxf(c[mt][nt][1] + bias[cc + 1], 0.f);
                *reinterpret_cast<float2*>(&C[(size_t)r * 64 + cc]) = make_float2(v0 * os, v1 * os);
            }
            int r2 = r + 8;
            if (r2 < M) {
                float os = outscale[r2];
                float v0 = fmaxf(c[mt][nt][2] + bias[cc], 0.f);
                float v1 = fmaxf(c[mt][nt][3] + bias[cc + 1], 0.f);
                *reinterpret_cast<float2*>(&C[(size_t)r2 * 64 + cc]) = make_float2(v0 * os, v1 * os);
            }
        }
    }
}

// ---------------- input gather (layer 1): raw features -> padded [N x KP] ------
// out[d, 0:FIN] = dinv[d] * ( dinv[d]*x[d] + sum_e dinv[s_e]*x[s_e] ); tail zero
template <int FIN, int KP>
__global__ __launch_bounds__(256) void gather_in(
    const float* __restrict__ x, const int* __restrict__ rp, const int* __restrict__ cnt,
    const int* __restrict__ esrc, const float* __restrict__ dinv,
    float* __restrict__ out, int N)
{
    int node = (int)((blockIdx.x * blockDim.x + threadIdx.x) >> 5);
    if (node >= N) return;
    int lane = threadIdx.x & 31;
    constexpr int R = (KP + 31) / 32;
    float acc[R];
    float dn = dinv[node];

    #pragma unroll
    for (int j = 0; j < R; j++) {
        int cc = lane + 32 * j;
        acc[j] = (cc < FIN) ? dn * x[(size_t)node * FIN + cc] : 0.f;
    }

    int start = rp[node], len = cnt[node];
    for (int base = 0; base < len; base += 32) {
        int valid = (base + lane < len);
        int myidx = valid ? esrc[start + base + lane] : 0;
        float myds = valid ? dinv[myidx] : 0.f;
        int m = min(32, len - base);
        for (int j = 0; j < m; j++) {
            int s = __shfl_sync(0xffffffffu, myidx, j);
            float ds = __shfl_sync(0xffffffffu, myds, j);
            const float* p = x + (size_t)s * FIN;
            #pragma unroll
            for (int q = 0; q < R; q++) {
                int cc = lane + 32 * q;
                if (cc < FIN) acc[q] = fmaf(ds, p[cc], acc[q]);
            }
        }
    }

    #pragma unroll
    for (int j = 0; j < R; j++) {
        int cc = lane + 32 * j;
        if (cc < KP) out[(size_t)node * KP + cc] = acc[j] * dn;
    }
}

// ---------------- hidden gather (layers 2/3): input pre-scaled by dinv ---------
// out[d] = dinv[d] * ( y[d] + sum_e y[s_e] )
template <int F>
__global__ __launch_bounds__(256) void gather_mid(
    const float* __restrict__ h, const int* __restrict__ rp, const int* __restrict__ cnt,
    const int* __restrict__ esrc, const float* __restrict__ dinv,
    float* __restrict__ out, int N)
{
    int node = (int)((blockIdx.x * blockDim.x + threadIdx.x) >> 5);
    if (node >= N) return;
    int lane = threadIdx.x & 31;
    constexpr int R = F / 32;
    float acc[R];

    {
        const float* p = h + (size_t)node * F;
        if constexpr (F == 64) {
            float2 v = *reinterpret_cast<const float2*>(p + lane * 2);
            acc[0] = v.x; acc[1] = v.y;
        } else {
            float4 v = *reinterpret_cast<const float4*>(p + lane * 4);
            acc[0] = v.x; acc[1] = v.y; acc[2] = v.z; acc[3] = v.w;
        }
    }

    int start = rp[node], len = cnt[node];
    for (int base = 0; base < len; base += 32) {
        int myidx = (base + lane < len) ? esrc[start + base + lane] : 0;
        int m = min(32, len - base);
        for (int j = 0; j < m; j++) {
            int s = __shfl_sync(0xffffffffu, myidx, j);
            const float* p = h + (size_t)s * F;
            if constexpr (F == 64) {
                float2 v = *reinterpret_cast<const float2*>(p + lane * 2);
                acc[0] += v.x; acc[1] += v.y;
            } else {
                float4 v = *reinterpret_cast<const float4*>(p + lane * 4);
                acc[0] += v.x; acc[1] += v.y; acc[2] += v.z; acc[3] += v.w;
            }
        }
    }

    float di = dinv[node];
    float* o = out + (size_t)node * F;
    if constexpr (F == 64) {
        *reinterpret_cast<float2*>(o + lane * 2) = make_float2(acc[0] * di, acc[1] * di);
    } else {
        *reinterpret_cast<float4*>(o + lane * 4) =
            make_float4(acc[0] * di, acc[1] * di, acc[2] * di, acc[3] * di);
    }
}

// ---------------- segmented mean-pool (batch is sorted) ------------------------
__global__ void pool_seg(const float* __restrict__ x, const int* __restrict__ batch,
                         int N, float* __restrict__ cat, int off)
{
    int b = blockIdx.x;
    int l = 0, r = N;
    while (l < r) { int m = (l + r) >> 1; if (batch[m] < b) l = m + 1; else r = m; }
    int start = l;
    r = N;
    while (l < r) { int m = (l + r) >> 1; if (batch[m] < b + 1) l = m + 1; else r = m; }
    int end = l;
    int c = threadIdx.x;
    float s = 0.f;
    for (int i = start; i < end; i++)
        s += x[(size_t)i * 256 + c];
    float cnt = (float)(end - start);
    cat[b * 512 + off + c] = s / fmaxf(cnt, 1.f);
}

// ---------------- final linear head ----------------
__global__ void out_kernel(const float* __restrict__ X, const float* __restrict__ W,
                           const float* __restrict__ bias, float* __restrict__ out)
{
    int b = blockIdx.x;
    __shared__ float red[256];
    float s = 0.f;
    for (int k = threadIdx.x; k < 512; k += 256)
        s += X[b * 512 + k] * W[k];
    red[threadIdx.x] = s;
    __syncthreads();
    for (int off = 128; off > 0; off >>= 1) {
        if (threadIdx.x < off) red[threadIdx.x] += red[threadIdx.x + off];
        __syncthreads();
    }
    if (threadIdx.x == 0) out[b] = red[0] + bias[0];
}

// ---------------- host side ----------------
static inline void gemm_tc(const float* A, const float* B, int M, int N, int K,
                           float* C0, const float* os, const float* bias, int relu)
{
    dim3 grid(N / 128, (M + 127) / 128);
    sgemm_tf32<<<grid, 256>>>(A, B, M, N, K, C0, os, bias, relu);
}

template <int FIN, int KP>
static void run_branch(const float* x, int N, int E,
                       const int* src, const int* dst, const int* batch,
                       const float* W1, const float* b1,
                       const float* W2, const float* b2,
                       const float* W3, const float* b3,
                       float* A, float* C,
                       int* cnt, int* rp, int* cursor, int* esrc, int* part, float* dinv,
                       float* cat, int catoff)
{
    // CSR build (dst-keyed) + dinv
    zero_i<<<(N + 255) / 256, 256>>>(cnt, N);
    hist_k<<<(E + 255) / 256, 256>>>(cnt, dst, E);
    int nb = (N + 1023) / 1024;
    scan1<<<nb, 1024>>>(cnt, rp, part, N);
    scan2<<<1, 256>>>(part, nb);
    scan3<<<nb, 1024>>>(rp, part, cursor, N);
    bucket_fill<<<(E + 255) / 256, 256>>>(src, dst, cursor, esrc, E);
    dinv_k<<<(N + 255) / 256, 256>>>(dinv, cnt, N);

    int gblocks = (N * 32 + 255) / 256;

    // layer 1: gather raw x into padded [N x KP], then tf32 GEMM KP->64
    gather_in<FIN, KP><<<gblocks, 256>>>(x, rp, cnt, esrc, dinv, A, N);
    {
        dim3 grid(1, (N + 127) / 128);
        sgemm_tf32_n64<KP><<<grid, 256>>>(A, W1, N, FIN, C, dinv, b1);  // C = dinv*relu(.)
    }

    // layer 2: gather (64), tf32 GEMM 64->128
    gather_mid<64><<<gblocks, 256>>>(C, rp, cnt, esrc, dinv, A, N);
    gemm_tc(A, W2, N, 128, 64, C, /*outscale=*/dinv, b2, 1);            // C = dinv*relu(.)

    // layer 3: gather (128), tf32 GEMM 128->256, plain relu output
    gather_mid<128><<<gblocks, 256>>>(C, rp, cnt, esrc, dinv, A, N);
    gemm_tc(A, W3, N, 256, 128, C, /*outscale=*/nullptr, b3, 1);

    // segmented mean pool -> cat[:, catoff:catoff+256]
    pool_seg<<<NB, 256>>>(C, batch, N, cat, catoff);
}

extern "C" void kernel_launch(void* const* d_in, const int* in_sizes, int n_in,
                              void* d_out, int out_size)
{
    const float* p_x    = (const float*)d_in[0];
    const int*   p_ei   = (const int*)d_in[1];
    const int*   p_bat  = (const int*)d_in[2];
    const float* l_x    = (const float*)d_in[3];
    const int*   l_ei   = (const int*)d_in[4];
    const int*   l_bat  = (const int*)d_in[5];
    const float* p_W1 = (const float*)d_in[6],  *p_b1 = (const float*)d_in[7];
    const float* p_W2 = (const float*)d_in[8],  *p_b2 = (const float*)d_in[9];
    const float* p_W3 = (const float*)d_in[10], *p_b3 = (const float*)d_in[11];
    const float* l_W1 = (const float*)d_in[12], *l_b1 = (const float*)d_in[13];
    const float* l_W2 = (const float*)d_in[14], *l_b2 = (const float*)d_in[15];
    const float* l_W3 = (const float*)d_in[16], *l_b3 = (const float*)d_in[17];
    const float* fc1_W = (const float*)d_in[18], *fc1_b = (const float*)d_in[19];
    const float* fc2_W = (const float*)d_in[20], *fc2_b = (const float*)d_in[21];
    const float* out_W = (const float*)d_in[22], *out_b = (const float*)d_in[23];
    float* out = (float*)d_out;

    float *pA, *pC, *lA, *lC, *dinv, *cat, *fc1, *fc2;
    int *cnt, *rp, *cursor, *esrc, *part;
    cudaGetSymbolAddress((void**)&pA, g_pA);
    cudaGetSymbolAddress((void**)&pC, g_pC);
    cudaGetSymbolAddress((void**)&lA, g_lA);
    cudaGetSymbolAddress((void**)&lC, g_lC);
    cudaGetSymbolAddress((void**)&dinv, g_dinv);
    cudaGetSymbolAddress((void**)&cnt, g_cnt);
    cudaGetSymbolAddress((void**)&rp, g_rp);
    cudaGetSymbolAddress((void**)&cursor, g_cursor);
    cudaGetSymbolAddress((void**)&esrc, g_esrc);
    cudaGetSymbolAddress((void**)&part, g_part);
    cudaGetSymbolAddress((void**)&cat, g_cat);
    cudaGetSymbolAddress((void**)&fc1, g_fc1);
    cudaGetSymbolAddress((void**)&fc2, g_fc2);

    // p branch: src = p_ei[0:E], dst = p_ei[E:2E]; K=41 padded to 48
    run_branch<41, 48>(p_x, PN, PE, p_ei, p_ei + PE, p_bat,
                       p_W1, p_b1, p_W2, p_b2, p_W3, p_b3,
                       pA, pC, cnt, rp, cursor, esrc, part, dinv, cat, 0);

    // l branch; K=78 padded to 80
    run_branch<78, 80>(l_x, LN, LE, l_ei, l_ei + LE, l_bat,
                       l_W1, l_b1, l_W2, l_b2, l_W3, l_b3,
                       lA, lC, cnt, rp, cursor, esrc, part, dinv, cat, 256);

    // MLP head (tf32)
    gemm_tc(cat, fc1_W, NB, 1024, 512, fc1, nullptr, fc1_b, 1);
    gemm_tc(fc1, fc2_W, NB, 512, 1024, fc2, nullptr, fc2_b, 1);
    out_kernel<<<NB, 256>>>(fc2, out_W, out_b, out);
}

// round 16
// speedup vs baseline: 2.9544x; 1.0433x over previous
#include <cuda_runtime.h>
#include <math.h>
#include <stdint.h>

// Problem-fixed sizes
#define PN 200000
#define PE 800000
#define LN 100000
#define LE 400000
#define NB 512

// ---------------- scratch (static device globals; no allocation) ----------------
__device__ float g_pA[(size_t)PN * 256];
__device__ float g_pC[(size_t)PN * 256];
__device__ float g_lA[(size_t)LN * 256];
__device__ float g_lC[(size_t)LN * 256];
// p-branch CSR
__device__ float g_pdinv[PN];
__device__ int   g_pcnt[PN];
__device__ int   g_prp[PN];
__device__ int   g_pcursor[PN];
__device__ int   g_pesrc[PE];
__device__ int   g_ppart[1024];
// l-branch CSR
__device__ float g_ldinv[LN];
__device__ int   g_lcnt[LN];
__device__ int   g_lrp[LN];
__device__ int   g_lcursor[LN];
__device__ int   g_lesrc[LE];
__device__ int   g_lpart[1024];

__device__ float g_cat[NB * 512];
__device__ float g_fc1[NB * 1024];
__device__ float g_fc2[NB * 512];

// ---------------- CSR build ----------------
__global__ void zero_i(int* p, int n) {
    int i = blockIdx.x * blockDim.x + threadIdx.x;
    if (i < n) p[i] = 0;
}
__global__ void hist_k(int* cnt, const int* __restrict__ dst, int E) {
    int i = blockIdx.x * blockDim.x + threadIdx.x;
    if (i < E) atomicAdd(&cnt[dst[i]], 1);
}
__global__ __launch_bounds__(1024) void scan1(const int* __restrict__ in, int* __restrict__ out,
                                              int* __restrict__ part, int n) {
    __shared__ int s[1024];
    int i = blockIdx.x * 1024 + threadIdx.x;
    int v = (i < n) ? in[i] : 0;
    s[threadIdx.x] = v;
    __syncthreads();
    for (int off = 1; off < 1024; off <<= 1) {
        int t = (threadIdx.x >= off) ? s[threadIdx.x - off] : 0;
        __syncthreads();
        s[threadIdx.x] += t;
        __syncthreads();
    }
    if (i < n) out[i] = s[threadIdx.x] - v;
    if (threadIdx.x == 1023) part[blockIdx.x] = s[1023];
}
__global__ __launch_bounds__(256) void scan2(int* part, int nb) {
    __shared__ int s[256];
    int v = (threadIdx.x < nb) ? part[threadIdx.x] : 0;
    s[threadIdx.x] = v;
    __syncthreads();
    for (int off = 1; off < 256; off <<= 1) {
        int t = (threadIdx.x >= off) ? s[threadIdx.x - off] : 0;
        __syncthreads();
        s[threadIdx.x] += t;
        __syncthreads();
    }
    if (threadIdx.x < nb) part[threadIdx.x] = s[threadIdx.x] - v;
}
__global__ __launch_bounds__(1024) void scan3(int* __restrict__ out, const int* __restrict__ part,
                                              int* __restrict__ cursor, int n) {
    int i = blockIdx.x * 1024 + threadIdx.x;
    if (i < n) {
        int v = out[i] + part[blockIdx.x];
        out[i] = v;
        cursor[i] = v;
    }
}
__global__ void bucket_fill(const int* __restrict__ src, const int* __restrict__ dst,
                            int* __restrict__ cursor, int* __restrict__ esrc, int E) {
    int i = blockIdx.x * blockDim.x + threadIdx.x;
    if (i < E) {
        int pos = atomicAdd(&cursor[dst[i]], 1);
        esrc[pos] = src[i];
    }
}
__global__ void dinv_k(float* dinv, const int* __restrict__ cnt, int n) {
    int i = blockIdx.x * blockDim.x + threadIdx.x;
    if (i < n) dinv[i] = rsqrtf(1.0f + (float)cnt[i]);
}

// ---------------- tf32 helpers ----------------
__device__ __forceinline__ float to_tf32(float x) {
    float r;
    asm("cvt.rna.tf32.f32 %0, %1;" : "=f"(r) : "f"(x));
    return r;
}

// ---------------- tf32 tensor-core GEMM, BN=128 --------------------------------
__global__ __launch_bounds__(256) void sgemm_tf32(
    const float* __restrict__ A, const float* __restrict__ Bm,
    int M, int N, int K,
    float* __restrict__ C,
    const float* __restrict__ outscale,
    const float* __restrict__ bias, int do_relu)
{
    __shared__ float As[128][20];
    __shared__ float Bs[16][132];
    const int tid = threadIdx.x;
    const int lane = tid & 31;
    const int warp = tid >> 5;
    const int wm = warp & 1;
    const int wn = warp >> 1;
    const int row0 = blockIdx.y * 128;
    const int col0 = blockIdx.x * 128;

    float c[4][4][4];
    #pragma unroll
    for (int mt = 0; mt < 4; mt++)
        #pragma unroll
        for (int nt = 0; nt < 4; nt++)
            #pragma unroll
            for (int r = 0; r < 4; r++) c[mt][nt][r] = 0.f;

    const int qr = lane >> 2;
    const int qc = lane & 3;

    for (int kk = 0; kk < K; kk += 16) {
        #pragma unroll
        for (int f = tid; f < 512; f += 256) {
            int m = f >> 2;
            int kq = (f & 3) * 4;
            int gr = row0 + m;
            float4 v = make_float4(0.f, 0.f, 0.f, 0.f);
            if (gr < M)
                v = *reinterpret_cast<const float4*>(&A[(size_t)gr * K + kk + kq]);
            As[m][kq + 0] = to_tf32(v.x);
            As[m][kq + 1] = to_tf32(v.y);
            As[m][kq + 2] = to_tf32(v.z);
            As[m][kq + 3] = to_tf32(v.w);
        }
        #pragma unroll
        for (int f = tid; f < 512; f += 256) {
            int k = f >> 5;
            int nq = (f & 31) * 4;
            float4 v = *reinterpret_cast<const float4*>(&Bm[(size_t)(kk + k) * N + col0 + nq]);
            Bs[k][nq + 0] = to_tf32(v.x);
            Bs[k][nq + 1] = to_tf32(v.y);
            Bs[k][nq + 2] = to_tf32(v.z);
            Bs[k][nq + 3] = to_tf32(v.w);
        }
        __syncthreads();

        #pragma unroll
        for (int ks = 0; ks < 16; ks += 8) {
            uint32_t af[4][4];
            #pragma unroll
            for (int mt = 0; mt < 4; mt++) {
                int r = wm * 64 + mt * 16 + qr;
                af[mt][0] = __float_as_uint(As[r][ks + qc]);
                af[mt][1] = __float_as_uint(As[r + 8][ks + qc]);
                af[mt][2] = __float_as_uint(As[r][ks + qc + 4]);
                af[mt][3] = __float_as_uint(As[r + 8][ks + qc + 4]);
            }
            uint32_t bf[4][2];
            #pragma unroll
            for (int nt = 0; nt < 4; nt++) {
                int cb = wn * 32 + nt * 8 + qr;
                bf[nt][0] = __float_as_uint(Bs[ks + qc][cb]);
                bf[nt][1] = __float_as_uint(Bs[ks + 4 + qc][cb]);
            }
            #pragma unroll
            for (int mt = 0; mt < 4; mt++)
                #pragma unroll
                for (int nt = 0; nt < 4; nt++) {
                    asm volatile(
                        "mma.sync.aligned.m16n8k8.row.col.f32.tf32.tf32.f32 "
                        "{%0,%1,%2,%3}, {%4,%5,%6,%7}, {%8,%9}, {%0,%1,%2,%3};"
                        : "+f"(c[mt][nt][0]), "+f"(c[mt][nt][1]),
                          "+f"(c[mt][nt][2]), "+f"(c[mt][nt][3])
                        : "r"(af[mt][0]), "r"(af[mt][1]), "r"(af[mt][2]), "r"(af[mt][3]),
                          "r"(bf[nt][0]), "r"(bf[nt][1]));
                }
        }
        __syncthreads();
    }

    #pragma unroll
    for (int mt = 0; mt < 4; mt++) {
        #pragma unroll
        for (int nt = 0; nt < 4; nt++) {
            int r = row0 + wm * 64 + mt * 16 + qr;
            int cc = col0 + wn * 32 + nt * 8 + 2 * qc;
            if (r < M) {
                float os = outscale ? outscale[r] : 1.f;
                float v0 = c[mt][nt][0] + bias[cc];
                float v1 = c[mt][nt][1] + bias[cc + 1];
                if (do_relu) { v0 = fmaxf(v0, 0.f); v1 = fmaxf(v1, 0.f); }
                *reinterpret_cast<float2*>(&C[(size_t)r * N + cc]) = make_float2(v0 * os, v1 * os);
            }
            int r2 = r + 8;
            if (r2 < M) {
                float os = outscale ? outscale[r2] : 1.f;
                float v0 = c[mt][nt][2] + bias[cc];
                float v1 = c[mt][nt][3] + bias[cc + 1];
                if (do_relu) { v0 = fmaxf(v0, 0.f); v1 = fmaxf(v1, 0.f); }
                *reinterpret_cast<float2*>(&C[(size_t)r2 * N + cc]) = make_float2(v0 * os, v1 * os);
            }
        }
    }
}

// ---------------- tf32 GEMM, BN=64 (layer 1) -----------------------------------
template<int KP>
__global__ __launch_bounds__(256) void sgemm_tf32_n64(
    const float* __restrict__ A, const float* __restrict__ Bm,
    int M, int Kact,
    float* __restrict__ C,
    const float* __restrict__ outscale,
    const float* __restrict__ bias)
{
    constexpr int AS = KP + 4;
    __shared__ float As[128][AS];
    __shared__ float Bs[16][68];
    const int tid = threadIdx.x;
    const int lane = tid & 31;
    const int warp = tid >> 5;
    const int wm = warp & 1;
    const int wn = warp >> 1;
    const int row0 = blockIdx.y * 128;

    float c[4][2][4];
    #pragma unroll
    for (int mt = 0; mt < 4; mt++)
        #pragma unroll
        for (int nt = 0; nt < 2; nt++)
            #pragma unroll
            for (int r = 0; r < 4; r++) c[mt][nt][r] = 0.f;

    const int qr = lane >> 2;
    const int qc = lane & 3;

    #pragma unroll
    for (int f = tid; f < 128 * KP / 4; f += 256) {
        int m = f / (KP / 4);
        int kq = (f % (KP / 4)) * 4;
        int gr = row0 + m;
        float4 v = make_float4(0.f, 0.f, 0.f, 0.f);
        if (gr < M)
            v = *reinterpret_cast<const float4*>(&A[(size_t)gr * KP + kq]);
        As[m][kq + 0] = to_tf32(v.x);
        As[m][kq + 1] = to_tf32(v.y);
        As[m][kq + 2] = to_tf32(v.z);
        As[m][kq + 3] = to_tf32(v.w);
    }

    for (int kk = 0; kk < KP; kk += 16) {
        #pragma unroll
        for (int f = tid; f < 256; f += 256) {
            int k = f >> 4;
            int nq = (f & 15) * 4;
            int gk = kk + k;
            float4 v = make_float4(0.f, 0.f, 0.f, 0.f);
            if (gk < Kact)
                v = *reinterpret_cast<const float4*>(&Bm[(size_t)gk * 64 + nq]);
            Bs[k][nq + 0] = to_tf32(v.x);
            Bs[k][nq + 1] = to_tf32(v.y);
            Bs[k][nq + 2] = to_tf32(v.z);
            Bs[k][nq + 3] = to_tf32(v.w);
        }
        __syncthreads();

        #pragma unroll
        for (int ks = 0; ks < 16; ks += 8) {
            uint32_t af[4][4];
            #pragma unroll
            for (int mt = 0; mt < 4; mt++) {
                int r = wm * 64 + mt * 16 + qr;
                af[mt][0] = __float_as_uint(As[r][kk + ks + qc]);
                af[mt][1] = __float_as_uint(As[r + 8][kk + ks + qc]);
                af[mt][2] = __float_as_uint(As[r][kk + ks + qc + 4]);
                af[mt][3] = __float_as_uint(As[r + 8][kk + ks + qc + 4]);
            }
            uint32_t bf[2][2];
            #pragma unroll
            for (int nt = 0; nt < 2; nt++) {
                int cb = wn * 16 + nt * 8 + qr;
                bf[nt][0] = __float_as_uint(Bs[ks + qc][cb]);
                bf[nt][1] = __float_as_uint(Bs[ks + 4 + qc][cb]);
            }
            #pragma unroll
            for (int mt = 0; mt < 4; mt++)
                #pragma unroll
                for (int nt = 0; nt < 2; nt++) {
                    asm volatile(
                        "mma.sync.aligned.m16n8k8.row.col.f32.tf32.tf32.f32 "
                        "{%0,%1,%2,%3}, {%4,%5,%6,%7}, {%8,%9}, {%0,%1,%2,%3};"
                        : "+f"(c[mt][nt][0]), "+f"(c[mt][nt][1]),
                          "+f"(c[mt][nt][2]), "+f"(c[mt][nt][3])
                        : "r"(af[mt][0]), "r"(af[mt][1]), "r"(af[mt][2]), "r"(af[mt][3]),
                          "r"(bf[nt][0]), "r"(bf[nt][1]));
                }
        }
        __syncthreads();
    }

    #pragma unroll
    for (int mt = 0; mt < 4; mt++) {
        #pragma unroll
        for (int nt = 0; nt < 2; nt++) {
            int r = row0 + wm * 64 + mt * 16 + qr;
            int cc = wn * 16 + nt * 8 + 2 * qc;
            if (r < M) {
                float os = outscale[r];
                float v0 = fmaxf(c[mt][nt][0] + bias[cc], 0.f);
                float v1 = fmaxf(c[mt][nt][1] + bias[cc + 1], 0.f);
                *reinterpret_cast<float2*>(&C[(size_t)r * 64 + cc]) = make_float2(v0 * os, v1 * os);
            }
            int r2 = r + 8;
            if (r2 < M) {
                float os = outscale[r2];
                float v0 = fmaxf(c[mt][nt][2] + bias[cc], 0.f);
                float v1 = fmaxf(c[mt][nt][3] + bias[cc + 1], 0.f);
                *reinterpret_cast<float2*>(&C[(size_t)r2 * 64 + cc]) = make_float2(v0 * os, v1 * os);
            }
        }
    }
}

// ---------------- input gather (layer 1): raw features -> padded [N x KP] ------
template <int FIN, int KP>
__global__ __launch_bounds__(256) void gather_in(
    const float* __restrict__ x, const int* __restrict__ rp, const int* __restrict__ cnt,
    const int* __restrict__ esrc, const float* __restrict__ dinv,
    float* __restrict__ out, int N)
{
    int node = (int)((blockIdx.x * blockDim.x + threadIdx.x) >> 5);
    if (node >= N) return;
    int lane = threadIdx.x & 31;
    constexpr int R = (KP + 31) / 32;
    float acc[R];
    float dn = dinv[node];

    #pragma unroll
    for (int j = 0; j < R; j++) {
        int cc = lane + 32 * j;
        acc[j] = (cc < FIN) ? dn * x[(size_t)node * FIN + cc] : 0.f;
    }

    int start = rp[node], len = cnt[node];
    for (int base = 0; base < len; base += 32) {
        int valid = (base + lane < len);
        int myidx = valid ? esrc[start + base + lane] : 0;
        float myds = valid ? dinv[myidx] : 0.f;
        int m = min(32, len - base);
        for (int j = 0; j < m; j++) {
            int s = __shfl_sync(0xffffffffu, myidx, j);
            float ds = __shfl_sync(0xffffffffu, myds, j);
            const float* p = x + (size_t)s * FIN;
            #pragma unroll
            for (int q = 0; q < R; q++) {
                int cc = lane + 32 * q;
                if (cc < FIN) acc[q] = fmaf(ds, p[cc], acc[q]);
            }
        }
    }

    #pragma unroll
    for (int j = 0; j < R; j++) {
        int cc = lane + 32 * j;
        if (cc < KP) out[(size_t)node * KP + cc] = acc[j] * dn;
    }
}

// ---------------- hidden gather (layers 2/3) -----------------------------------
template <int F>
__global__ __launch_bounds__(256) void gather_mid(
    const float* __restrict__ h, const int* __restrict__ rp, const int* __restrict__ cnt,
    const int* __restrict__ esrc, const float* __restrict__ dinv,
    float* __restrict__ out, int N)
{
    int node = (int)((blockIdx.x * blockDim.x + threadIdx.x) >> 5);
    if (node >= N) return;
    int lane = threadIdx.x & 31;
    constexpr int R = F / 32;
    float acc[R];

    {
        const float* p = h + (size_t)node * F;
        if constexpr (F == 64) {
            float2 v = *reinterpret_cast<const float2*>(p + lane * 2);
            acc[0] = v.x; acc[1] = v.y;
        } else {
            float4 v = *reinterpret_cast<const float4*>(p + lane * 4);
            acc[0] = v.x; acc[1] = v.y; acc[2] = v.z; acc[3] = v.w;
        }
    }

    int start = rp[node], len = cnt[node];
    for (int base = 0; base < len; base += 32) {
        int myidx = (base + lane < len) ? esrc[start + base + lane] : 0;
        int m = min(32, len - base);
        for (int j = 0; j < m; j++) {
            int s = __shfl_sync(0xffffffffu, myidx, j);
            const float* p = h + (size_t)s * F;
            if constexpr (F == 64) {
                float2 v = *reinterpret_cast<const float2*>(p + lane * 2);
                acc[0] += v.x; acc[1] += v.y;
            } else {
                float4 v = *reinterpret_cast<const float4*>(p + lane * 4);
                acc[0] += v.x; acc[1] += v.y; acc[2] += v.z; acc[3] += v.w;
            }
        }
    }

    float di = dinv[node];
    float* o = out + (size_t)node * F;
    if constexpr (F == 64) {
        *reinterpret_cast<float2*>(o + lane * 2) = make_float2(acc[0] * di, acc[1] * di);
    } else {
        *reinterpret_cast<float4*>(o + lane * 4) =
            make_float4(acc[0] * di, acc[1] * di, acc[2] * di, acc[3] * di);
    }
}

// ---------------- segmented mean-pool (batch is sorted) ------------------------
__global__ void pool_seg(const float* __restrict__ x, const int* __restrict__ batch,
                         int N, float* __restrict__ cat, int off)
{
    int b = blockIdx.x;
    int l = 0, r = N;
    while (l < r) { int m = (l + r) >> 1; if (batch[m] < b) l = m + 1; else r = m; }
    int start = l;
    r = N;
    while (l < r) { int m = (l + r) >> 1; if (batch[m] < b + 1) l = m + 1; else r = m; }
    int end = l;
    int c = threadIdx.x;
    float s = 0.f;
    for (int i = start; i < end; i++)
        s += x[(size_t)i * 256 + c];
    float cnt = (float)(end - start);
    cat[b * 512 + off + c] = s / fmaxf(cnt, 1.f);
}

// ---------------- final linear head ----------------
__global__ void out_kernel(const float* __restrict__ X, const float* __restrict__ W,
                           const float* __restrict__ bias, float* __restrict__ out)
{
    int b = blockIdx.x;
    __shared__ float red[256];
    float s = 0.f;
    for (int k = threadIdx.x; k < 512; k += 256)
        s += X[b * 512 + k] * W[k];
    red[threadIdx.x] = s;
    __syncthreads();
    for (int off = 128; off > 0; off >>= 1) {
        if (threadIdx.x < off) red[threadIdx.x] += red[threadIdx.x + off];
        __syncthreads();
    }
    if (threadIdx.x == 0) out[b] = red[0] + bias[0];
}

// ---------------- host side ----------------
static inline void gemm_tc(cudaStream_t st, const float* A, const float* B,
                           int M, int N, int K,
                           float* C0, const float* os, const float* bias, int relu)
{
    dim3 grid(N / 128, (M + 127) / 128);
    sgemm_tf32<<<grid, 256, 0, st>>>(A, B, M, N, K, C0, os, bias, relu);
}

template <int FIN, int KP>
static void run_branch(cudaStream_t st,
                       const float* x, int N, int E,
                       const int* src, const int* dst, const int* batch,
                       const float* W1, const float* b1,
                       const float* W2, const float* b2,
                       const float* W3, const float* b3,
                       float* A, float* C,
                       int* cnt, int* rp, int* cursor, int* esrc, int* part, float* dinv,
                       float* cat, int catoff)
{
    // CSR build (dst-keyed) + dinv
    zero_i<<<(N + 255) / 256, 256, 0, st>>>(cnt, N);
    hist_k<<<(E + 255) / 256, 256, 0, st>>>(cnt, dst, E);
    int nb = (N + 1023) / 1024;
    scan1<<<nb, 1024, 0, st>>>(cnt, rp, part, N);
    scan2<<<1, 256, 0, st>>>(part, nb);
    scan3<<<nb, 1024, 0, st>>>(rp, part, cursor, N);
    bucket_fill<<<(E + 255) / 256, 256, 0, st>>>(src, dst, cursor, esrc, E);
    dinv_k<<<(N + 255) / 256, 256, 0, st>>>(dinv, cnt, N);

    int gblocks = (N * 32 + 255) / 256;

    // layer 1: gather raw x into padded [N x KP], then tf32 GEMM KP->64
    gather_in<FIN, KP><<<gblocks, 256, 0, st>>>(x, rp, cnt, esrc, dinv, A, N);
    {
        dim3 grid(1, (N + 127) / 128);
        sgemm_tf32_n64<KP><<<grid, 256, 0, st>>>(A, W1, N, FIN, C, dinv, b1);
    }

    // layer 2: gather (64), tf32 GEMM 64->128
    gather_mid<64><<<gblocks, 256, 0, st>>>(C, rp, cnt, esrc, dinv, A, N);
    gemm_tc(st, A, W2, N, 128, 64, C, dinv, b2, 1);

    // layer 3: gather (128), tf32 GEMM 128->256, plain relu output
    gather_mid<128><<<gblocks, 256, 0, st>>>(C, rp, cnt, esrc, dinv, A, N);
    gemm_tc(st, A, W3, N, 256, 128, C, nullptr, b3, 1);

    // segmented mean pool -> cat[:, catoff:catoff+256]
    pool_seg<<<NB, 256, 0, st>>>(C, batch, N, cat, catoff);
}

extern "C" void kernel_launch(void* const* d_in, const int* in_sizes, int n_in,
                              void* d_out, int out_size)
{
    const float* p_x    = (const float*)d_in[0];
    const int*   p_ei   = (const int*)d_in[1];
    const int*   p_bat  = (const int*)d_in[2];
    const float* l_x    = (const float*)d_in[3];
    const int*   l_ei   = (const int*)d_in[4];
    const int*   l_bat  = (const int*)d_in[5];
    const float* p_W1 = (const float*)d_in[6],  *p_b1 = (const float*)d_in[7];
    const float* p_W2 = (const float*)d_in[8],  *p_b2 = (const float*)d_in[9];
    const float* p_W3 = (const float*)d_in[10], *p_b3 = (const float*)d_in[11];
    const float* l_W1 = (const float*)d_in[12], *l_b1 = (const float*)d_in[13];
    const float* l_W2 = (const float*)d_in[14], *l_b2 = (const float*)d_in[15];
    const float* l_W3 = (const float*)d_in[16], *l_b3 = (const float*)d_in[17];
    const float* fc1_W = (const float*)d_in[18], *fc1_b = (const float*)d_in[19];
    const float* fc2_W = (const float*)d_in[20], *fc2_b = (const float*)d_in[21];
    const float* out_W = (const float*)d_in[22], *out_b = (const float*)d_in[23];
    float* out = (float*)d_out;

    float *pA, *pC, *lA, *lC, *pdinv, *ldinv, *cat, *fc1, *fc2;
    int *pcnt, *prp, *pcursor, *pesrc, *ppart;
    int *lcnt, *lrp, *lcursor, *lesrc, *lpart;
    cudaGetSymbolAddress((void**)&pA, g_pA);
    cudaGetSymbolAddress((void**)&pC, g_pC);
    cudaGetSymbolAddress((void**)&lA, g_lA);
    cudaGetSymbolAddress((void**)&lC, g_lC);
    cudaGetSymbolAddress((void**)&pdinv, g_pdinv);
    cudaGetSymbolAddress((void**)&pcnt, g_pcnt);
    cudaGetSymbolAddress((void**)&prp, g_prp);
    cudaGetSymbolAddress((void**)&pcursor, g_pcursor);
    cudaGetSymbolAddress((void**)&pesrc, g_pesrc);
    cudaGetSymbolAddress((void**)&ppart, g_ppart);
    cudaGetSymbolAddress((void**)&ldinv, g_ldinv);
    cudaGetSymbolAddress((void**)&lcnt, g_lcnt);
    cudaGetSymbolAddress((void**)&lrp, g_lrp);
    cudaGetSymbolAddress((void**)&lcursor, g_lcursor);
    cudaGetSymbolAddress((void**)&lesrc, g_lesrc);
    cudaGetSymbolAddress((void**)&lpart, g_lpart);
    cudaGetSymbolAddress((void**)&cat, g_cat);
    cudaGetSymbolAddress((void**)&fc1, g_fc1);
    cudaGetSymbolAddress((void**)&fc2, g_fc2);

    // Fork a second stream for the l-branch (graph-capture fork-join).
    // Streams/events are host objects; created per call (kernel_launch runs
    // only for the correctness pass and the capture pass). Leaked deliberately:
    // destroying capture-associated handles before EndCapture is risky.
    cudaStream_t s2;
    cudaStreamCreateWithFlags(&s2, cudaStreamNonBlocking);
    cudaEvent_t evFork, evJoin;
    cudaEventCreateWithFlags(&evFork, cudaEventDisableTiming);
    cudaEventCreateWithFlags(&evJoin, cudaEventDisableTiming);

    cudaEventRecord(evFork, 0);          // origin (legacy) stream
    cudaStreamWaitEvent(s2, evFork, 0);  // s2 joins the capture

    // p branch on the origin stream
    run_branch<41, 48>((cudaStream_t)0, p_x, PN, PE, p_ei, p_ei + PE, p_bat,
                       p_W1, p_b1, p_W2, p_b2, p_W3, p_b3,
                       pA, pC, pcnt, prp, pcursor, pesrc, ppart, pdinv, cat, 0);

    // l branch concurrently on s2
    run_branch<78, 80>(s2, l_x, LN, LE, l_ei, l_ei + LE, l_bat,
                       l_W1, l_b1, l_W2, l_b2, l_W3, l_b3,
                       lA, lC, lcnt, lrp, lcursor, lesrc, lpart, ldinv, cat, 256);

    cudaEventRecord(evJoin, s2);
    cudaStreamWaitEvent(0, evJoin, 0);   // join back before the head

    // MLP head (tf32) on the origin stream
    gemm_tc((cudaStream_t)0, cat, fc1_W, NB, 1024, 512, fc1, nullptr, fc1_b, 1);
    gemm_tc((cudaStream_t)0, fc1, fc2_W, NB, 512, 1024, fc2, nullptr, fc2_b, 1);
    out_kernel<<<NB, 256, 0, 0>>>(fc2, out_W, out_b, out);
}